// round 2
// baseline (speedup 1.0000x reference)
#include <cuda_runtime.h>

// ---------------------------------------------------------------------------
// GraphDecoder decode-step, GB300 baseline (fp32 SIMT tiled SGEMM framework).
//
// Structure (6 GEMM launches + 1 tiny weight-assembly kernel):
//   K0: assemble block-diagonal W2 [1536 x 69] (padded to 72) + bias[69]
//   K1: hist  = relu([znode | bond_onehot]            @ wbond_w + wbond_b)   K=516
//   K2: cur   = relu([hist | atom_onehot]             @ rbond_w + rbond_b)   K=576
//   K3: h_t   = relu([gvec | xnode | ctx(gather)]     @ topo_w1 + topo_b1)   K=1152
//   K4: h_a   = relu([gvec | xnode | ctx(gather)]     @ atom_w1 + atom_b1)   K=1152
//   K5: h_b   = relu([gvec | cur | znode | ctx]       @ bond_w1 + bond_b1)   K=1664
//   K6: out   =      [h_t | h_a | h_b]                @ W2blk   + b2blk      K=1536, N=69
//
// A-operand is a virtual concatenation of up to 4 row-major segments, one of
// which may be row-gathered via batch_idx (ctx = src_graph_vecs[batch_idx]).
// ---------------------------------------------------------------------------

#define M_ROWS 32768
#define HDIM   512
#define LDIM   128
#define ADIM   64
#define NBDIM  4

#define BM 128
#define BN 128
#define BK 8
#define TM 8
#define TN 8
// threads per block = (BM/TM)*(BN/TN) = 256

struct Seg { const float* ptr; int width; int gather; };
struct Segs { Seg s[4]; };

// Scratch (allocation-free rule: __device__ globals)
__device__ float g_hist[(size_t)M_ROWS * HDIM];
__device__ float g_cur [(size_t)M_ROWS * HDIM];
__device__ float g_ht  [(size_t)M_ROWS * HDIM];
__device__ float g_ha  [(size_t)M_ROWS * HDIM];
__device__ float g_hb  [(size_t)M_ROWS * HDIM];
__device__ float g_w2  [1536 * 72];   // padded row stride 72, zero-filled
__device__ float g_b2  [72];

// ---------------------------------------------------------------------------
// K0: build block-diagonal second-layer weights + bias
// ---------------------------------------------------------------------------
__global__ void build_w2_kernel(const float* __restrict__ topo_w2,
                                const float* __restrict__ topo_b2,
                                const float* __restrict__ atom_w2,
                                const float* __restrict__ atom_b2,
                                const float* __restrict__ bond_w2,
                                const float* __restrict__ bond_b2)
{
    int i = blockIdx.x * blockDim.x + threadIdx.x;
    const int total = 1536 * 72;
    if (i < total) {
        int k = i / 72;
        int n = i - k * 72;
        float v = 0.0f;
        if (n == 0) {
            if (k < 512) v = topo_w2[k];                       // [512,1]
        } else if (n < 65) {
            if (k >= 512 && k < 1024) v = atom_w2[(k - 512) * 64 + (n - 1)];  // [512,64]
        } else if (n < 69) {
            if (k >= 1024) v = bond_w2[(k - 1024) * 4 + (n - 65)];            // [512,4]
        }
        g_w2[i] = v;
    }
    if (i < 72) {
        float b = 0.0f;
        if (i == 0)      b = topo_b2[0];
        else if (i < 65) b = atom_b2[i - 1];
        else if (i < 69) b = bond_b2[i - 65];
        g_b2[i] = b;
    }
}

// ---------------------------------------------------------------------------
// Segmented-A tiled SGEMM:  C[M,N] = act(A_concat[M,K] @ B[K,N](ldb) + bias)
// All segment widths are multiples of 4 -> float4 A loads never straddle a
// segment boundary. Rows beyond K (when K % BK != 0) read as zero; B rows
// beyond K read as zero. N may be < BN (guarded).
// ---------------------------------------------------------------------------
template <int NSEG, bool RELU>
__global__ __launch_bounds__(256, 2)
void sgemm_seg(int N, int K,
               Segs segs, const int* __restrict__ batch_idx,
               const float* __restrict__ B, int ldb,
               const float* __restrict__ bias,
               float* __restrict__ C, int ldc)
{
    __shared__ __align__(16) float As[BK][BM];
    __shared__ __align__(16) float Bs[BK][BN];

    const int bm  = blockIdx.x * BM;
    const int bn  = blockIdx.y * BN;
    const int tid = threadIdx.x;

    const int tr = (tid >> 4) * TM;   // 0..120 step 8 (row offset in tile)
    const int tc = (tid & 15) * TN;   // 0..120 step 8 (col offset in tile)

    // A tile load mapping: 128 rows x 8 cols, one float4 per thread
    const int a_row = tid >> 1;           // 0..127
    const int a_col = (tid & 1) << 2;     // 0 or 4
    // B tile load mapping: 8 rows x 128 cols, one float4 per thread
    const int b_row = tid >> 5;           // 0..7
    const int b_col = (tid & 31) << 2;    // 0..124

    const int grow = bm + a_row;          // global A row (M is multiple of BM)

    // Per-segment row base pointers (gather resolved once)
    const float* abase[NSEG];
    int          awidth[NSEG];
#pragma unroll
    for (int s = 0; s < NSEG; ++s) {
        int r = segs.s[s].gather ? batch_idx[grow] : grow;
        abase[s]  = segs.s[s].ptr + (size_t)r * segs.s[s].width;
        awidth[s] = segs.s[s].width;
    }

    float acc[TM][TN];
#pragma unroll
    for (int i = 0; i < TM; ++i)
#pragma unroll
        for (int j = 0; j < TN; ++j) acc[i][j] = 0.0f;

    for (int k0 = 0; k0 < K; k0 += BK) {
        // ---- load A float4 (segmented, zero-padded past K) ----
        float4 av = make_float4(0.f, 0.f, 0.f, 0.f);
        {
            int c = k0 + a_col;
#pragma unroll
            for (int s = 0; s < NSEG; ++s) {
                if (c >= 0 && c < awidth[s])
                    av = *reinterpret_cast<const float4*>(abase[s] + c);
                c -= awidth[s];
            }
        }
        As[a_col + 0][a_row] = av.x;
        As[a_col + 1][a_row] = av.y;
        As[a_col + 2][a_row] = av.z;
        As[a_col + 3][a_row] = av.w;

        // ---- load B float4 (zero past K rows / N cols) ----
        float4 bv = make_float4(0.f, 0.f, 0.f, 0.f);
        {
            int brow = k0 + b_row;
            int bcol = bn + b_col;
            if (brow < K && bcol < N)
                bv = *reinterpret_cast<const float4*>(B + (size_t)brow * ldb + bcol);
        }
        *reinterpret_cast<float4*>(&Bs[b_row][b_col]) = bv;

        __syncthreads();

#pragma unroll
        for (int k = 0; k < BK; ++k) {
            float4 m0 = *reinterpret_cast<const float4*>(&As[k][tr]);
            float4 m1 = *reinterpret_cast<const float4*>(&As[k][tr + 4]);
            float4 n0 = *reinterpret_cast<const float4*>(&Bs[k][tc]);
            float4 n1 = *reinterpret_cast<const float4*>(&Bs[k][tc + 4]);
            float rm[TM] = {m0.x, m0.y, m0.z, m0.w, m1.x, m1.y, m1.z, m1.w};
            float rn[TN] = {n0.x, n0.y, n0.z, n0.w, n1.x, n1.y, n1.z, n1.w};
#pragma unroll
            for (int i = 0; i < TM; ++i)
#pragma unroll
                for (int j = 0; j < TN; ++j)
                    acc[i][j] = fmaf(rm[i], rn[j], acc[i][j]);
        }
        __syncthreads();
    }

    // ---- epilogue: bias + optional relu ----
#pragma unroll
    for (int i = 0; i < TM; ++i) {
        const size_t m = (size_t)(bm + tr + i);
#pragma unroll
        for (int j = 0; j < TN; ++j) {
            int n = bn + tc + j;
            if (n < N) {
                float v = acc[i][j] + bias[n];
                if (RELU) v = fmaxf(v, 0.0f);
                C[m * ldc + n] = v;
            }
        }
    }
}

// ---------------------------------------------------------------------------
// Launch
// ---------------------------------------------------------------------------
extern "C" void kernel_launch(void* const* d_in, const int* in_sizes, int n_in,
                              void* d_out, int out_size)
{
    (void)in_sizes; (void)n_in; (void)out_size;

    const float* src_graph_vecs = (const float*)d_in[0];   // [1024,128]
    const float* gvec           = (const float*)d_in[1];   // [32768,512]
    const float* xnode          = (const float*)d_in[2];   // [32768,512]
    const float* znode          = (const float*)d_in[3];   // [32768,512]
    const float* atom_onehot    = (const float*)d_in[4];   // [32768,64]
    const float* bond_onehot    = (const float*)d_in[5];   // [32768,4]
    const float* topo_w1        = (const float*)d_in[6];   // [1152,512]
    const float* topo_b1        = (const float*)d_in[7];
    const float* topo_w2        = (const float*)d_in[8];   // [512,1]
    const float* topo_b2        = (const float*)d_in[9];
    const float* atom_w1        = (const float*)d_in[10];  // [1152,512]
    const float* atom_b1        = (const float*)d_in[11];
    const float* atom_w2        = (const float*)d_in[12];  // [512,64]
    const float* atom_b2        = (const float*)d_in[13];
    const float* bond_w1        = (const float*)d_in[14];  // [1664,512]
    const float* bond_b1        = (const float*)d_in[15];
    const float* bond_w2        = (const float*)d_in[16];  // [512,4]
    const float* bond_b2        = (const float*)d_in[17];
    const float* rbond_w        = (const float*)d_in[18];  // [576,512]
    const float* rbond_b        = (const float*)d_in[19];
    const float* wbond_w        = (const float*)d_in[20];  // [516,512]
    const float* wbond_b        = (const float*)d_in[21];
    const int*   batch_idx      = (const int*)d_in[22];    // [32768]
    float*       out            = (float*)d_out;           // [32768,69]

    float *hist, *cur, *ht, *ha, *hb, *w2, *b2;
    cudaGetSymbolAddress((void**)&hist, g_hist);
    cudaGetSymbolAddress((void**)&cur,  g_cur);
    cudaGetSymbolAddress((void**)&ht,   g_ht);
    cudaGetSymbolAddress((void**)&ha,   g_ha);
    cudaGetSymbolAddress((void**)&hb,   g_hb);
    cudaGetSymbolAddress((void**)&w2,   g_w2);
    cudaGetSymbolAddress((void**)&b2,   g_b2);

    // K0: assemble block-diagonal scoring weights
    build_w2_kernel<<<(1536 * 72 + 255) / 256, 256>>>(
        topo_w2, topo_b2, atom_w2, atom_b2, bond_w2, bond_b2);

    const dim3 blk(256);
    const dim3 grid512(M_ROWS / BM, HDIM / BN);   // (256, 4)
    const dim3 grid69(M_ROWS / BM, 1);            // (256, 1)

    // K1: hist = relu([znode | bond_onehot] @ wbond_w + wbond_b), K=516
    {
        Segs s; s.s[0] = {znode, HDIM, 0}; s.s[1] = {bond_onehot, NBDIM, 0};
        s.s[2] = {nullptr, 0, 0}; s.s[3] = {nullptr, 0, 0};
        sgemm_seg<2, true><<<grid512, blk>>>(HDIM, HDIM + NBDIM, s, batch_idx,
                                             wbond_w, HDIM, wbond_b, hist, HDIM);
    }
    // K3: h_t = relu([gvec | xnode | ctx] @ topo_w1 + topo_b1), K=1152
    {
        Segs s; s.s[0] = {gvec, HDIM, 0}; s.s[1] = {xnode, HDIM, 0};
        s.s[2] = {src_graph_vecs, LDIM, 1}; s.s[3] = {nullptr, 0, 0};
        sgemm_seg<3, true><<<grid512, blk>>>(HDIM, 2 * HDIM + LDIM, s, batch_idx,
                                             topo_w1, HDIM, topo_b1, ht, HDIM);
    }
    // K4: h_a = relu([gvec | xnode | ctx] @ atom_w1 + atom_b1), K=1152
    {
        Segs s; s.s[0] = {gvec, HDIM, 0}; s.s[1] = {xnode, HDIM, 0};
        s.s[2] = {src_graph_vecs, LDIM, 1}; s.s[3] = {nullptr, 0, 0};
        sgemm_seg<3, true><<<grid512, blk>>>(HDIM, 2 * HDIM + LDIM, s, batch_idx,
                                             atom_w1, HDIM, atom_b1, ha, HDIM);
    }
    // K2: cur = relu([hist | atom_onehot] @ rbond_w + rbond_b), K=576
    {
        Segs s; s.s[0] = {hist, HDIM, 0}; s.s[1] = {atom_onehot, ADIM, 0};
        s.s[2] = {nullptr, 0, 0}; s.s[3] = {nullptr, 0, 0};
        sgemm_seg<2, true><<<grid512, blk>>>(HDIM, HDIM + ADIM, s, batch_idx,
                                             rbond_w, HDIM, rbond_b, cur, HDIM);
    }
    // K5: h_b = relu([gvec | cur | znode | ctx] @ bond_w1 + bond_b1), K=1664
    {
        Segs s; s.s[0] = {gvec, HDIM, 0}; s.s[1] = {cur, HDIM, 0};
        s.s[2] = {znode, HDIM, 0}; s.s[3] = {src_graph_vecs, LDIM, 1};
        sgemm_seg<4, true><<<grid512, blk>>>(HDIM, 3 * HDIM + LDIM, s, batch_idx,
                                             bond_w1, HDIM, bond_b1, hb, HDIM);
    }
    // K6: out = [h_t | h_a | h_b] @ W2blk + b2blk, K=1536, N=69 (ldb padded 72)
    {
        Segs s; s.s[0] = {ht, HDIM, 0}; s.s[1] = {ha, HDIM, 0};
        s.s[2] = {hb, HDIM, 0}; s.s[3] = {nullptr, 0, 0};
        sgemm_seg<3, false><<<grid69, blk>>>(69, 3 * HDIM, s, batch_idx,
                                             w2, 72, b2, out, 69);
    }
}

// round 3
// speedup vs baseline: 4.0145x; 4.0145x over previous
#include <cuda_runtime.h>
#include <cstdint>

// ---------------------------------------------------------------------------
// GraphDecoder decode-step — TF32 mma.sync tensor-core version.
//
//   K0: assemble block-diagonal W2 [1536 x 69->72] + bias
//   K1: hist  = relu([znode | bond_onehot]        @ wbond_w)   K=516
//   K2: cur   = relu([hist | atom_onehot]         @ rbond_w)   K=576
//   K3: h_t   = relu([gvec | xnode | ctx(gather)] @ topo_w1)   K=1152
//   K4: h_a   = relu([gvec | xnode | ctx(gather)] @ atom_w1)   K=1152
//   K5: h_b   = relu([gvec | cur | znode | ctx]   @ bond_w1)   K=1664
//   K6: out   = [h_t | h_a | h_b] @ W2blk + b2blk              K=1536, N=69
//
// GEMM core: BM=128 BN=128 BK=32, 256 thr, 8 warps x (64x32) warp tile,
// mma.sync.aligned.m16n8k8.row.col.f32.tf32.tf32.f32, cp.async double buffer.
// ---------------------------------------------------------------------------

#define M_ROWS 32768
#define HDIM   512
#define LDIM   128
#define ADIM   64
#define NBDIM  4

#define BM 128
#define BN 128
#define BK 32
#define ASTRIDE 36            // floats; bank = (4*row + k) % 32 -> conflict-free
#define BSTRIDE 136           // floats; bank = (8*k + n) % 32  -> conflict-free
#define ASZ (BM * ASTRIDE)    // 4608 floats
#define BSZ (BK * BSTRIDE)    // 4352 floats
#define STAGE (ASZ + BSZ)     // 8960 floats = 35840 B
#define SMEM_BYTES (2 * STAGE * 4)  // 71680 B

struct Seg { const float* ptr; int width; int gather; };
struct Segs { Seg s[4]; };

// Scratch (__device__ globals: allocation-free rule)
__device__ float g_hist[(size_t)M_ROWS * HDIM];
__device__ float g_cur [(size_t)M_ROWS * HDIM];
__device__ float g_ht  [(size_t)M_ROWS * HDIM];
__device__ float g_ha  [(size_t)M_ROWS * HDIM];
__device__ float g_hb  [(size_t)M_ROWS * HDIM];
__device__ float g_w2  [1536 * 72 + 64];   // zero-init tail pads OOB-ish reads
__device__ float g_b2  [72];

// ---------------------------------------------------------------------------
__global__ void build_w2_kernel(const float* __restrict__ topo_w2,
                                const float* __restrict__ topo_b2,
                                const float* __restrict__ atom_w2,
                                const float* __restrict__ atom_b2,
                                const float* __restrict__ bond_w2,
                                const float* __restrict__ bond_b2)
{
    int i = blockIdx.x * blockDim.x + threadIdx.x;
    const int total = 1536 * 72;
    if (i < total) {
        int k = i / 72;
        int n = i - k * 72;
        float v = 0.0f;
        if (n == 0) {
            if (k < 512) v = topo_w2[k];
        } else if (n < 65) {
            if (k >= 512 && k < 1024) v = atom_w2[(k - 512) * 64 + (n - 1)];
        } else if (n < 69) {
            if (k >= 1024) v = bond_w2[(k - 1024) * 4 + (n - 65)];
        }
        g_w2[i] = v;
    }
    if (i < 72) {
        float b = 0.0f;
        if (i == 0)      b = topo_b2[0];
        else if (i < 65) b = atom_b2[i - 1];
        else if (i < 69) b = bond_b2[i - 65];
        g_b2[i] = b;
    }
}

// ---------------------------------------------------------------------------
__device__ __forceinline__ void cp_async16(void* smem_dst, const void* gsrc, int src_bytes)
{
    uint32_t d = (uint32_t)__cvta_generic_to_shared(smem_dst);
    asm volatile("cp.async.cg.shared.global [%0], [%1], 16, %2;\n"
                 :: "r"(d), "l"(gsrc), "r"(src_bytes));
}
__device__ __forceinline__ uint32_t f2tf32(float x)
{
    uint32_t r;
    asm("cvt.rna.tf32.f32 %0, %1;" : "=r"(r) : "f"(x));
    return r;
}
__device__ __forceinline__ void mma_tf32(float* c, const uint32_t* a, const uint32_t* b)
{
    asm volatile(
        "mma.sync.aligned.m16n8k8.row.col.f32.tf32.tf32.f32 "
        "{%0,%1,%2,%3}, {%4,%5,%6,%7}, {%8,%9}, {%0,%1,%2,%3};"
        : "+f"(c[0]), "+f"(c[1]), "+f"(c[2]), "+f"(c[3])
        : "r"(a[0]), "r"(a[1]), "r"(a[2]), "r"(a[3]), "r"(b[0]), "r"(b[1]));
}

// ---------------------------------------------------------------------------
// Segmented-A TF32 GEMM:  C[M,N] = act(A_concat[M,K] @ B[K,N](ldb) + bias)
// Segment widths are multiples of 4 (16B cp.async never straddles a boundary).
// ---------------------------------------------------------------------------
template <int NSEG, bool RELU>
__global__ __launch_bounds__(256, 2)
void mma_seg(int N, int K,
             Segs segs, const int* __restrict__ batch_idx,
             const float* __restrict__ B, int ldb,
             const float* __restrict__ bias,
             float* __restrict__ C, int ldc)
{
    extern __shared__ float smem[];

    const int bm   = blockIdx.x * BM;
    const int bn   = blockIdx.y * BN;
    const int tid  = threadIdx.x;
    const int lane = tid & 31;
    const int warp = tid >> 5;
    const int wm   = warp >> 2;   // 0..1  -> m offset wm*64
    const int wn   = warp & 3;    // 0..3  -> n offset wn*32

    // ---- A-load row bookkeeping (4 passes of 32 rows) ----
    bool needGather = false;
#pragma unroll
    for (int s = 0; s < NSEG; ++s) needGather |= (segs.s[s].gather != 0);

    int grows[4], gidx[4];
#pragma unroll
    for (int p = 0; p < 4; ++p) {
        grows[p] = bm + p * 32 + (tid >> 3);
        gidx[p]  = needGather ? batch_idx[grows[p]] : 0;
    }
    const int acolq = (tid & 7) * 4;      // A k-offset within tile (0..28)
    const int bcolq = (tid & 31) * 4;     // B n-offset within tile (0..124)
    const int browq = tid >> 5;           // B k-row base (0..7), +8 per pass

    const int nk = (K + BK - 1) / BK;

    float acc[4][4][4];
#pragma unroll
    for (int mt = 0; mt < 4; ++mt)
#pragma unroll
        for (int nt = 0; nt < 4; ++nt)
#pragma unroll
            for (int i = 0; i < 4; ++i) acc[mt][nt][i] = 0.0f;

    // ---- tile loader ----
    auto load_tile = [&](int kt, int buf) {
        float* As = smem + buf * STAGE;
        float* Bs = smem + buf * STAGE + ASZ;
        const int k0 = kt * BK;

        // A: resolve segment for this thread's column (same for all passes)
        const int col = k0 + acolq;
        const float* sptr = segs.s[0].ptr;
        int swid = 1, sgat = 0, cloc = 0;
        bool valid = false;
        int cc = col;
#pragma unroll
        for (int s = 0; s < NSEG; ++s) {
            if (cc >= 0 && cc < segs.s[s].width) {
                sptr = segs.s[s].ptr; swid = segs.s[s].width;
                sgat = segs.s[s].gather; cloc = cc; valid = true;
            }
            cc -= segs.s[s].width;
        }
#pragma unroll
        for (int p = 0; p < 4; ++p) {
            int row = p * 32 + (tid >> 3);
            float* dst = As + row * ASTRIDE + acolq;
            const float* src;
            int sb;
            if (valid) {
                long r = sgat ? gidx[p] : grows[p];
                src = sptr + (size_t)r * swid + cloc;
                sb = 16;
            } else {
                src = sptr;   // dummy valid address, zero-fill
                sb = 0;
            }
            cp_async16(dst, src, sb);
        }
        // B
#pragma unroll
        for (int p = 0; p < 4; ++p) {
            int brow = p * 8 + browq;
            float* dst = Bs + brow * BSTRIDE + bcolq;
            int gr = k0 + brow;
            const float* src = (gr < K) ? (B + (size_t)gr * ldb + bn + bcolq) : B;
            int sb = (gr < K) ? 16 : 0;
            cp_async16(dst, src, sb);
        }
        asm volatile("cp.async.commit_group;\n" ::);
    };

    // ---- pipeline ----
    load_tile(0, 0);
    int buf = 0;
    for (int kt = 0; kt < nk; ++kt) {
        if (kt + 1 < nk) {
            load_tile(kt + 1, buf ^ 1);
            asm volatile("cp.async.wait_group 1;\n" ::);
        } else {
            asm volatile("cp.async.wait_group 0;\n" ::);
        }
        __syncthreads();

        const float* As = smem + buf * STAGE;
        const float* Bs = smem + buf * STAGE + ASZ;

#pragma unroll
        for (int k8 = 0; k8 < BK; k8 += 8) {
            uint32_t a[4][4], b[4][2];
#pragma unroll
            for (int mt = 0; mt < 4; ++mt) {
                const float* p = As + (wm * 64 + mt * 16 + (lane >> 2)) * ASTRIDE
                               + k8 + (lane & 3);
                a[mt][0] = f2tf32(p[0]);
                a[mt][1] = f2tf32(p[8 * ASTRIDE]);
                a[mt][2] = f2tf32(p[4]);
                a[mt][3] = f2tf32(p[8 * ASTRIDE + 4]);
            }
#pragma unroll
            for (int nt = 0; nt < 4; ++nt) {
                const float* p = Bs + (k8 + (lane & 3)) * BSTRIDE
                               + wn * 32 + nt * 8 + (lane >> 2);
                b[nt][0] = f2tf32(p[0]);
                b[nt][1] = f2tf32(p[4 * BSTRIDE]);
            }
#pragma unroll
            for (int mt = 0; mt < 4; ++mt)
#pragma unroll
                for (int nt = 0; nt < 4; ++nt)
                    mma_tf32(acc[mt][nt], a[mt], b[nt]);
        }
        __syncthreads();
        buf ^= 1;
    }

    // ---- epilogue: bias + relu + store ----
#pragma unroll
    for (int mt = 0; mt < 4; ++mt) {
        const int r0 = bm + wm * 64 + mt * 16 + (lane >> 2);
#pragma unroll
        for (int nt = 0; nt < 4; ++nt) {
            const int c0 = bn + wn * 32 + nt * 8 + (lane & 3) * 2;
            float bv0 = (c0     < N) ? bias[c0]     : 0.0f;
            float bv1 = (c0 + 1 < N) ? bias[c0 + 1] : 0.0f;
            float v00 = acc[mt][nt][0] + bv0;
            float v01 = acc[mt][nt][1] + bv1;
            float v10 = acc[mt][nt][2] + bv0;
            float v11 = acc[mt][nt][3] + bv1;
            if (RELU) {
                v00 = fmaxf(v00, 0.0f); v01 = fmaxf(v01, 0.0f);
                v10 = fmaxf(v10, 0.0f); v11 = fmaxf(v11, 0.0f);
            }
            if (c0 < N) {
                C[(size_t)r0 * ldc + c0]       = v00;
                C[(size_t)(r0 + 8) * ldc + c0] = v10;
            }
            if (c0 + 1 < N) {
                C[(size_t)r0 * ldc + c0 + 1]       = v01;
                C[(size_t)(r0 + 8) * ldc + c0 + 1] = v11;
            }
        }
    }
}

// ---------------------------------------------------------------------------
extern "C" void kernel_launch(void* const* d_in, const int* in_sizes, int n_in,
                              void* d_out, int out_size)
{
    (void)in_sizes; (void)n_in; (void)out_size;

    const float* src_graph_vecs = (const float*)d_in[0];
    const float* gvec           = (const float*)d_in[1];
    const float* xnode          = (const float*)d_in[2];
    const float* znode          = (const float*)d_in[3];
    const float* atom_onehot    = (const float*)d_in[4];
    const float* bond_onehot    = (const float*)d_in[5];
    const float* topo_w1        = (const float*)d_in[6];
    const float* topo_b1        = (const float*)d_in[7];
    const float* topo_w2        = (const float*)d_in[8];
    const float* topo_b2        = (const float*)d_in[9];
    const float* atom_w1        = (const float*)d_in[10];
    const float* atom_b1        = (const float*)d_in[11];
    const float* atom_w2        = (const float*)d_in[12];
    const float* atom_b2        = (const float*)d_in[13];
    const float* bond_w1        = (const float*)d_in[14];
    const float* bond_b1        = (const float*)d_in[15];
    const float* bond_w2        = (const float*)d_in[16];
    const float* bond_b2        = (const float*)d_in[17];
    const float* rbond_w        = (const float*)d_in[18];
    const float* rbond_b        = (const float*)d_in[19];
    const float* wbond_w        = (const float*)d_in[20];
    const float* wbond_b        = (const float*)d_in[21];
    const int*   batch_idx      = (const int*)d_in[22];
    float*       out            = (float*)d_out;

    float *hist, *cur, *ht, *ha, *hb, *w2, *b2;
    cudaGetSymbolAddress((void**)&hist, g_hist);
    cudaGetSymbolAddress((void**)&cur,  g_cur);
    cudaGetSymbolAddress((void**)&ht,   g_ht);
    cudaGetSymbolAddress((void**)&ha,   g_ha);
    cudaGetSymbolAddress((void**)&hb,   g_hb);
    cudaGetSymbolAddress((void**)&w2,   g_w2);
    cudaGetSymbolAddress((void**)&b2,   g_b2);

    // Allow >48KB dynamic smem (idempotent; not a stream op — capture-safe)
    cudaFuncSetAttribute(mma_seg<2, true>,
        cudaFuncAttributeMaxDynamicSharedMemorySize, SMEM_BYTES);
    cudaFuncSetAttribute(mma_seg<3, true>,
        cudaFuncAttributeMaxDynamicSharedMemorySize, SMEM_BYTES);
    cudaFuncSetAttribute(mma_seg<4, true>,
        cudaFuncAttributeMaxDynamicSharedMemorySize, SMEM_BYTES);
    cudaFuncSetAttribute(mma_seg<3, false>,
        cudaFuncAttributeMaxDynamicSharedMemorySize, SMEM_BYTES);

    build_w2_kernel<<<(1536 * 72 + 255) / 256, 256>>>(
        topo_w2, topo_b2, atom_w2, atom_b2, bond_w2, bond_b2);

    const dim3 blk(256);
    const dim3 grid512(M_ROWS / BM, HDIM / BN);   // (256, 4)
    const dim3 grid69(M_ROWS / BM, 1);            // (256, 1)

    // K1: hist = relu([znode | bond_onehot] @ wbond_w + wbond_b), K=516
    {
        Segs s; s.s[0] = {znode, HDIM, 0}; s.s[1] = {bond_onehot, NBDIM, 0};
        s.s[2] = {nullptr, 0, 0}; s.s[3] = {nullptr, 0, 0};
        mma_seg<2, true><<<grid512, blk, SMEM_BYTES>>>(
            HDIM, HDIM + NBDIM, s, batch_idx, wbond_w, HDIM, wbond_b, hist, HDIM);
    }
    // K3: h_t = relu([gvec | xnode | ctx] @ topo_w1 + topo_b1), K=1152
    {
        Segs s; s.s[0] = {gvec, HDIM, 0}; s.s[1] = {xnode, HDIM, 0};
        s.s[2] = {src_graph_vecs, LDIM, 1}; s.s[3] = {nullptr, 0, 0};
        mma_seg<3, true><<<grid512, blk, SMEM_BYTES>>>(
            HDIM, 2 * HDIM + LDIM, s, batch_idx, topo_w1, HDIM, topo_b1, ht, HDIM);
    }
    // K4: h_a = relu([gvec | xnode | ctx] @ atom_w1 + atom_b1), K=1152
    {
        Segs s; s.s[0] = {gvec, HDIM, 0}; s.s[1] = {xnode, HDIM, 0};
        s.s[2] = {src_graph_vecs, LDIM, 1}; s.s[3] = {nullptr, 0, 0};
        mma_seg<3, true><<<grid512, blk, SMEM_BYTES>>>(
            HDIM, 2 * HDIM + LDIM, s, batch_idx, atom_w1, HDIM, atom_b1, ha, HDIM);
    }
    // K2: cur = relu([hist | atom_onehot] @ rbond_w + rbond_b), K=576
    {
        Segs s; s.s[0] = {hist, HDIM, 0}; s.s[1] = {atom_onehot, ADIM, 0};
        s.s[2] = {nullptr, 0, 0}; s.s[3] = {nullptr, 0, 0};
        mma_seg<2, true><<<grid512, blk, SMEM_BYTES>>>(
            HDIM, HDIM + ADIM, s, batch_idx, rbond_w, HDIM, rbond_b, cur, HDIM);
    }
    // K5: h_b = relu([gvec | cur | znode | ctx] @ bond_w1 + bond_b1), K=1664
    {
        Segs s; s.s[0] = {gvec, HDIM, 0}; s.s[1] = {cur, HDIM, 0};
        s.s[2] = {znode, HDIM, 0}; s.s[3] = {src_graph_vecs, LDIM, 1};
        mma_seg<4, true><<<grid512, blk, SMEM_BYTES>>>(
            HDIM, 3 * HDIM + LDIM, s, batch_idx, bond_w1, HDIM, bond_b1, hb, HDIM);
    }
    // K6: out = [h_t | h_a | h_b] @ W2blk + b2blk, K=1536, N=69 (ldb=72)
    {
        Segs s; s.s[0] = {ht, HDIM, 0}; s.s[1] = {ha, HDIM, 0};
        s.s[2] = {hb, HDIM, 0}; s.s[3] = {nullptr, 0, 0};
        mma_seg<3, false><<<grid69, blk, SMEM_BYTES>>>(
            69, 3 * HDIM, s, batch_idx, w2, 72, b2, out, 69);
    }
}

// round 4
// speedup vs baseline: 7.4276x; 1.8502x over previous
#include <cuda_runtime.h>
#include <cuda_fp16.h>
#include <cstdint>

// ---------------------------------------------------------------------------
// GraphDecoder decode-step — fp16 mma.sync (m16n8k16, fp32 accum).
//
// Pre-pass: round inputs to fp16 scratch, materialize ctx gather, pad
// bond_onehot 4->8, transpose all weights to [N, Kpad] fp16, build
// block-diagonal W2^T [128 x 1536] + bias[72].
// GEMMs (BM=128 BN=128 BK=64, 256 thr, 8 warps x 64x32):
//   K1: hist = relu([znode | boh8]        @ wbond)  K=520
//   K3: h_t  = relu([gvec | xnode | ctx]  @ topo)   K=1152
//   K4: h_a  = relu([gvec | xnode | ctx]  @ atom)   K=1152
//   K2: cur  = relu([hist | aoh]          @ rbond)  K=576
//   K5: h_b  = relu([gvec|cur|znode|ctx]  @ bond)   K=1664
//   K6: out  = [h_t|h_a|h_b] @ W2t + b2             K=1536, N=69 (f32 out)
// ---------------------------------------------------------------------------

#define M_ROWS 32768
#define BM 128
#define BN 128
#define BK 64
#define ASTR 72                        // halfs per row (64 data + 8 pad); word stride 36 == 4 mod 32
#define ATILE_H (BM * ASTR)            // 9216 halfs
#define STAGE_H (2 * ATILE_H)          // A + B per stage
#define SMEM_BYTES (2 * STAGE_H * 2)   // 73728 B

struct SegH { const __half* ptr; int width; };
struct SegsH { SegH s[4]; };

// ----- fp16 scratch (__device__ globals; allocation-free rule) -----
__device__ __half g_gvec_h [(size_t)M_ROWS * 512];
__device__ __half g_xnode_h[(size_t)M_ROWS * 512];
__device__ __half g_znode_h[(size_t)M_ROWS * 512];
__device__ __half g_ctx_h  [(size_t)M_ROWS * 128];
__device__ __half g_aoh_h  [(size_t)M_ROWS * 64];
__device__ __half g_boh_h  [(size_t)M_ROWS * 8];
__device__ __half g_hist_h [(size_t)M_ROWS * 512];
__device__ __half g_cur_h  [(size_t)M_ROWS * 512];
__device__ __half g_ht_h   [(size_t)M_ROWS * 512];
__device__ __half g_ha_h   [(size_t)M_ROWS * 512];
__device__ __half g_hb_h   [(size_t)M_ROWS * 512];
__device__ __half g_wt_topo [512 * 1152];
__device__ __half g_wt_atom [512 * 1152];
__device__ __half g_wt_bond [512 * 1664];
__device__ __half g_wt_rbond[512 * 576];
__device__ __half g_wt_wbond[512 * 520];
__device__ __half g_w2t     [128 * 1536];
__device__ float  g_b2[72];

// ---------------------------------------------------------------------------
// Pre-pass kernels
// ---------------------------------------------------------------------------
__global__ void cvt_f2h(const float* __restrict__ in, __half* __restrict__ out, int n)
{
    int i = (blockIdx.x * blockDim.x + threadIdx.x) * 4;
    if (i + 3 < n) {
        float4 v = *reinterpret_cast<const float4*>(in + i);
        __half2 h0 = __floats2half2_rn(v.x, v.y);
        __half2 h1 = __floats2half2_rn(v.z, v.w);
        *reinterpret_cast<__half2*>(out + i)     = h0;
        *reinterpret_cast<__half2*>(out + i + 2) = h1;
    } else {
        for (; i < n; ++i) out[i] = __float2half_rn(in[i]);
    }
}

__global__ void gather_ctx(const float* __restrict__ src, const int* __restrict__ idx,
                           __half* __restrict__ out)
{
    int i = blockIdx.x * blockDim.x + threadIdx.x;   // over M*128/4
    int m = i >> 5;                                  // 128/4 = 32 float4 per row
    int j = (i & 31) * 4;
    float4 v = *reinterpret_cast<const float4*>(src + (size_t)idx[m] * 128 + j);
    __half2 h0 = __floats2half2_rn(v.x, v.y);
    __half2 h1 = __floats2half2_rn(v.z, v.w);
    __half* o = out + (size_t)m * 128 + j;
    *reinterpret_cast<__half2*>(o)     = h0;
    *reinterpret_cast<__half2*>(o + 2) = h1;
}

__global__ void pad_boh(const float* __restrict__ in, __half* __restrict__ out)
{
    int i = blockIdx.x * blockDim.x + threadIdx.x;   // over M*8
    int m = i >> 3;
    int j = i & 7;
    out[i] = (j < 4) ? __float2half_rn(in[m * 4 + j]) : __half(0.0f);
}

// w [Kin][N] f32 -> wt [N][Kpad] fp16 (rows n, zero-pad k >= Kin)
__global__ void transpose_w(const float* __restrict__ w, __half* __restrict__ wt,
                            int Kin, int Kpad, int N)
{
    int i = blockIdx.x * blockDim.x + threadIdx.x;
    if (i >= N * Kpad) return;
    int n = i / Kpad, k = i - n * Kpad;
    wt[i] = (k < Kin) ? __float2half_rn(w[(size_t)k * N + n]) : __half(0.0f);
}

// block-diagonal W2^T [128][1536] + bias[72]
__global__ void build_w2t(const float* __restrict__ tw2, const float* __restrict__ tb2,
                          const float* __restrict__ aw2, const float* __restrict__ ab2,
                          const float* __restrict__ bw2, const float* __restrict__ bb2)
{
    int i = blockIdx.x * blockDim.x + threadIdx.x;
    if (i < 128 * 1536) {
        int n = i / 1536, k = i - n * 1536;
        float v = 0.0f;
        if (n == 0) {
            if (k < 512) v = tw2[k];
        } else if (n < 65) {
            if (k >= 512 && k < 1024) v = aw2[(k - 512) * 64 + (n - 1)];
        } else if (n < 69) {
            if (k >= 1024) v = bw2[(k - 1024) * 4 + (n - 65)];
        }
        g_w2t[i] = __float2half_rn(v);
    }
    if (i < 72) {
        float b = 0.0f;
        if (i == 0)      b = tb2[0];
        else if (i < 65) b = ab2[i - 1];
        else if (i < 69) b = bb2[i - 65];
        g_b2[i] = b;
    }
}

// ---------------------------------------------------------------------------
__device__ __forceinline__ void cp_async16(void* smem_dst, const void* gsrc, int src_bytes)
{
    uint32_t d = (uint32_t)__cvta_generic_to_shared(smem_dst);
    asm volatile("cp.async.cg.shared.global [%0], [%1], 16, %2;\n"
                 :: "r"(d), "l"(gsrc), "r"(src_bytes));
}
__device__ __forceinline__ void mma_f16(float* c, const uint32_t* a, const uint32_t* b)
{
    asm volatile(
        "mma.sync.aligned.m16n8k16.row.col.f32.f16.f16.f32 "
        "{%0,%1,%2,%3}, {%4,%5,%6,%7}, {%8,%9}, {%0,%1,%2,%3};"
        : "+f"(c[0]), "+f"(c[1]), "+f"(c[2]), "+f"(c[3])
        : "r"(a[0]), "r"(a[1]), "r"(a[2]), "r"(a[3]), "r"(b[0]), "r"(b[1]));
}

// ---------------------------------------------------------------------------
// Segmented-A fp16 GEMM. A = concat of NSEG fp16 [M, w] buffers (w mult of 8),
// B = fp16 [N][ldb] (weights pre-transposed, k contiguous).
// OUTH: store fp16 (intermediate), else f32 (final, N guarded).
// ---------------------------------------------------------------------------
template <int NSEG, bool RELU, bool OUTH>
__global__ __launch_bounds__(256, 2)
void mma_h(int N, int K, SegsH segs,
           const __half* __restrict__ Bt, int ldb,
           const float* __restrict__ bias,
           void* __restrict__ Cv, int ldc)
{
    extern __shared__ __half sm[];

    const int bn   = blockIdx.x * BN;
    const int bm   = blockIdx.y * BM;
    const int tid  = threadIdx.x;
    const int lane = tid & 31;
    const int warp = tid >> 5;
    const int wm   = warp >> 2;   // 0..1 -> m offset wm*64
    const int wn   = warp & 3;    // 0..3 -> n offset wn*32

    const int arow = tid >> 3;    // 0..31 (+32 per pass)
    const int ac8  = tid & 7;     // 8-half chunk column

    const int nk = (K + BK - 1) / BK;

    float acc[4][4][4];
#pragma unroll
    for (int mt = 0; mt < 4; ++mt)
#pragma unroll
        for (int nt = 0; nt < 4; ++nt)
#pragma unroll
            for (int i = 0; i < 4; ++i) acc[mt][nt][i] = 0.0f;

    auto load_tile = [&](int kt, int buf) {
        __half* As = sm + buf * STAGE_H;
        __half* Bs = As + ATILE_H;
        const int k0 = kt * BK;

        // A: resolve segment for this thread's fixed column
        const int col = k0 + ac8 * 8;
        const __half* sptr = nullptr;
        int swid = 1, cloc = 0;
        bool valid = false;
        int cc = col;
#pragma unroll
        for (int s = 0; s < NSEG; ++s) {
            if (cc >= 0 && cc < segs.s[s].width) {
                sptr = segs.s[s].ptr; swid = segs.s[s].width; cloc = cc; valid = true;
            }
            cc -= segs.s[s].width;
        }
#pragma unroll
        for (int p = 0; p < 4; ++p) {
            int row = arow + 32 * p;
            __half* dst = As + row * ASTR + ac8 * 8;
            const void* src = valid ? (const void*)(sptr + (size_t)(bm + row) * swid + cloc)
                                    : (const void*)bias;
            cp_async16(dst, src, valid ? 16 : 0);
        }
        // B: rows = output cols (pre-transposed weights), k contiguous
        const int kc = k0 + ac8 * 8;
        const bool bvalid = (kc < K);
#pragma unroll
        for (int p = 0; p < 4; ++p) {
            int nrow = arow + 32 * p;
            __half* dst = Bs + nrow * ASTR + ac8 * 8;
            const void* src = bvalid ? (const void*)(Bt + (size_t)(bn + nrow) * ldb + kc)
                                     : (const void*)bias;
            cp_async16(dst, src, bvalid ? 16 : 0);
        }
        asm volatile("cp.async.commit_group;\n" ::);
    };

    load_tile(0, 0);
    int buf = 0;
    for (int kt = 0; kt < nk; ++kt) {
        if (kt + 1 < nk) {
            load_tile(kt + 1, buf ^ 1);
            asm volatile("cp.async.wait_group 1;\n" ::);
        } else {
            asm volatile("cp.async.wait_group 0;\n" ::);
        }
        __syncthreads();

        const __half* As = sm + buf * STAGE_H;
        const __half* Bs = As + ATILE_H;

#pragma unroll
        for (int s = 0; s < BK / 16; ++s) {         // 4 k16 steps
            const int kh = s * 16 + (lane & 3) * 2; // half offset within row
            uint32_t a[4][4], b[4][2];
#pragma unroll
            for (int mt = 0; mt < 4; ++mt) {
                const __half* p = As + (wm * 64 + mt * 16 + (lane >> 2)) * ASTR + kh;
                a[mt][0] = *reinterpret_cast<const uint32_t*>(p);
                a[mt][1] = *reinterpret_cast<const uint32_t*>(p + 8 * ASTR);
                a[mt][2] = *reinterpret_cast<const uint32_t*>(p + 8);
                a[mt][3] = *reinterpret_cast<const uint32_t*>(p + 8 * ASTR + 8);
            }
#pragma unroll
            for (int nt = 0; nt < 4; ++nt) {
                const __half* p = Bs + (wn * 32 + nt * 8 + (lane >> 2)) * ASTR + kh;
                b[nt][0] = *reinterpret_cast<const uint32_t*>(p);
                b[nt][1] = *reinterpret_cast<const uint32_t*>(p + 8);
            }
#pragma unroll
            for (int mt = 0; mt < 4; ++mt)
#pragma unroll
                for (int nt = 0; nt < 4; ++nt)
                    mma_f16(acc[mt][nt], a[mt], b[nt]);
        }
        __syncthreads();
        buf ^= 1;
    }

    // ---- epilogue ----
#pragma unroll
    for (int mt = 0; mt < 4; ++mt) {
        const int r0 = bm + wm * 64 + mt * 16 + (lane >> 2);
#pragma unroll
        for (int nt = 0; nt < 4; ++nt) {
            const int c0 = bn + wn * 32 + nt * 8 + (lane & 3) * 2;
            float bv0 = (c0     < N) ? bias[c0]     : 0.0f;
            float bv1 = (c0 + 1 < N) ? bias[c0 + 1] : 0.0f;
            float v00 = acc[mt][nt][0] + bv0;
            float v01 = acc[mt][nt][1] + bv1;
            float v10 = acc[mt][nt][2] + bv0;
            float v11 = acc[mt][nt][3] + bv1;
            if (RELU) {
                v00 = fmaxf(v00, 0.0f); v01 = fmaxf(v01, 0.0f);
                v10 = fmaxf(v10, 0.0f); v11 = fmaxf(v11, 0.0f);
            }
            if (OUTH) {
                __half* C = (__half*)Cv;
                *reinterpret_cast<__half2*>(C + (size_t)r0 * ldc + c0)
                    = __floats2half2_rn(v00, v01);
                *reinterpret_cast<__half2*>(C + (size_t)(r0 + 8) * ldc + c0)
                    = __floats2half2_rn(v10, v11);
            } else {
                float* C = (float*)Cv;
                if (c0 < N) {
                    C[(size_t)r0 * ldc + c0]       = v00;
                    C[(size_t)(r0 + 8) * ldc + c0] = v10;
                }
                if (c0 + 1 < N) {
                    C[(size_t)r0 * ldc + c0 + 1]       = v01;
                    C[(size_t)(r0 + 8) * ldc + c0 + 1] = v11;
                }
            }
        }
    }
}

// ---------------------------------------------------------------------------
extern "C" void kernel_launch(void* const* d_in, const int* in_sizes, int n_in,
                              void* d_out, int out_size)
{
    (void)in_sizes; (void)n_in; (void)out_size;

    const float* src_graph_vecs = (const float*)d_in[0];
    const float* gvec           = (const float*)d_in[1];
    const float* xnode          = (const float*)d_in[2];
    const float* znode          = (const float*)d_in[3];
    const float* atom_onehot    = (const float*)d_in[4];
    const float* bond_onehot    = (const float*)d_in[5];
    const float* topo_w1        = (const float*)d_in[6];
    const float* topo_b1        = (const float*)d_in[7];
    const float* topo_w2        = (const float*)d_in[8];
    const float* topo_b2        = (const float*)d_in[9];
    const float* atom_w1        = (const float*)d_in[10];
    const float* atom_b1        = (const float*)d_in[11];
    const float* atom_w2        = (const float*)d_in[12];
    const float* atom_b2        = (const float*)d_in[13];
    const float* bond_w1        = (const float*)d_in[14];
    const float* bond_b1        = (const float*)d_in[15];
    const float* bond_w2        = (const float*)d_in[16];
    const float* bond_b2        = (const float*)d_in[17];
    const float* rbond_w        = (const float*)d_in[18];
    const float* rbond_b        = (const float*)d_in[19];
    const float* wbond_w        = (const float*)d_in[20];
    const float* wbond_b        = (const float*)d_in[21];
    const int*   batch_idx      = (const int*)d_in[22];
    float*       out            = (float*)d_out;

    __half *gvh, *xnh, *znh, *ctxh, *aohh, *bohh;
    __half *histh, *curh, *hth, *hah, *hbh;
    __half *wtT, *wtA, *wtB, *wtR, *wtW, *w2t;
    float  *b2;
    cudaGetSymbolAddress((void**)&gvh,   g_gvec_h);
    cudaGetSymbolAddress((void**)&xnh,   g_xnode_h);
    cudaGetSymbolAddress((void**)&znh,   g_znode_h);
    cudaGetSymbolAddress((void**)&ctxh,  g_ctx_h);
    cudaGetSymbolAddress((void**)&aohh,  g_aoh_h);
    cudaGetSymbolAddress((void**)&bohh,  g_boh_h);
    cudaGetSymbolAddress((void**)&histh, g_hist_h);
    cudaGetSymbolAddress((void**)&curh,  g_cur_h);
    cudaGetSymbolAddress((void**)&hth,   g_ht_h);
    cudaGetSymbolAddress((void**)&hah,   g_ha_h);
    cudaGetSymbolAddress((void**)&hbh,   g_hb_h);
    cudaGetSymbolAddress((void**)&wtT,   g_wt_topo);
    cudaGetSymbolAddress((void**)&wtA,   g_wt_atom);
    cudaGetSymbolAddress((void**)&wtB,   g_wt_bond);
    cudaGetSymbolAddress((void**)&wtR,   g_wt_rbond);
    cudaGetSymbolAddress((void**)&wtW,   g_wt_wbond);
    cudaGetSymbolAddress((void**)&w2t,   g_w2t);
    cudaGetSymbolAddress((void**)&b2,    g_b2);

    cudaFuncSetAttribute(mma_h<2, true, true>,
        cudaFuncAttributeMaxDynamicSharedMemorySize, SMEM_BYTES);
    cudaFuncSetAttribute(mma_h<3, true, true>,
        cudaFuncAttributeMaxDynamicSharedMemorySize, SMEM_BYTES);
    cudaFuncSetAttribute(mma_h<4, true, true>,
        cudaFuncAttributeMaxDynamicSharedMemorySize, SMEM_BYTES);
    cudaFuncSetAttribute(mma_h<3, false, false>,
        cudaFuncAttributeMaxDynamicSharedMemorySize, SMEM_BYTES);

    // ---- pre-pass ----
    const int M = M_ROWS;
    cvt_f2h<<<(M * 512 / 4 + 255) / 256, 256>>>(gvec,  gvh, M * 512);
    cvt_f2h<<<(M * 512 / 4 + 255) / 256, 256>>>(xnode, xnh, M * 512);
    cvt_f2h<<<(M * 512 / 4 + 255) / 256, 256>>>(znode, znh, M * 512);
    cvt_f2h<<<(M * 64  / 4 + 255) / 256, 256>>>(atom_onehot, aohh, M * 64);
    gather_ctx<<<(M * 32 + 255) / 256, 256>>>(src_graph_vecs, batch_idx, ctxh);
    pad_boh<<<(M * 8 + 255) / 256, 256>>>(bond_onehot, bohh);
    transpose_w<<<(512 * 1152 + 255) / 256, 256>>>(topo_w1, wtT, 1152, 1152, 512);
    transpose_w<<<(512 * 1152 + 255) / 256, 256>>>(atom_w1, wtA, 1152, 1152, 512);
    transpose_w<<<(512 * 1664 + 255) / 256, 256>>>(bond_w1, wtB, 1664, 1664, 512);
    transpose_w<<<(512 * 576  + 255) / 256, 256>>>(rbond_w, wtR, 576, 576, 512);
    transpose_w<<<(512 * 520  + 255) / 256, 256>>>(wbond_w, wtW, 516, 520, 512);
    build_w2t<<<(128 * 1536 + 255) / 256, 256>>>(topo_w2, topo_b2, atom_w2, atom_b2,
                                                 bond_w2, bond_b2);

    const dim3 blk(256);
    const dim3 grid512(4, M / BM);   // (n-tiles, m-tiles): n-tiles adjacent for L2 A-reuse
    const dim3 grid69(1, M / BM);

    // K1: hist = relu([znode | boh8] @ wbond), K=520
    {
        SegsH s; s.s[0] = {znh, 512}; s.s[1] = {bohh, 8};
        s.s[2] = {nullptr, 0}; s.s[3] = {nullptr, 0};
        mma_h<2, true, true><<<grid512, blk, SMEM_BYTES>>>(
            512, 520, s, wtW, 520, wbond_b, histh, 512);
    }
    // K3: h_t = relu([gvec | xnode | ctx] @ topo), K=1152
    {
        SegsH s; s.s[0] = {gvh, 512}; s.s[1] = {xnh, 512};
        s.s[2] = {ctxh, 128}; s.s[3] = {nullptr, 0};
        mma_h<3, true, true><<<grid512, blk, SMEM_BYTES>>>(
            512, 1152, s, wtT, 1152, topo_b1, hth, 512);
    }
    // K4: h_a = relu([gvec | xnode | ctx] @ atom), K=1152
    {
        SegsH s; s.s[0] = {gvh, 512}; s.s[1] = {xnh, 512};
        s.s[2] = {ctxh, 128}; s.s[3] = {nullptr, 0};
        mma_h<3, true, true><<<grid512, blk, SMEM_BYTES>>>(
            512, 1152, s, wtA, 1152, atom_b1, hah, 512);
    }
    // K2: cur = relu([hist | aoh] @ rbond), K=576
    {
        SegsH s; s.s[0] = {histh, 512}; s.s[1] = {aohh, 64};
        s.s[2] = {nullptr, 0}; s.s[3] = {nullptr, 0};
        mma_h<2, true, true><<<grid512, blk, SMEM_BYTES>>>(
            512, 576, s, wtR, 576, rbond_b, curh, 512);
    }
    // K5: h_b = relu([gvec | cur | znode | ctx] @ bond), K=1664
    {
        SegsH s; s.s[0] = {gvh, 512}; s.s[1] = {curh, 512};
        s.s[2] = {znh, 512}; s.s[3] = {ctxh, 128};
        mma_h<4, true, true><<<grid512, blk, SMEM_BYTES>>>(
            512, 1664, s, wtB, 1664, bond_b1, hbh, 512);
    }
    // K6: out = [h_t | h_a | h_b] @ W2t + b2, K=1536, N=69 (f32)
    {
        SegsH s; s.s[0] = {hth, 512}; s.s[1] = {hah, 512};
        s.s[2] = {hbh, 512}; s.s[3] = {nullptr, 0};
        mma_h<3, false, false><<<grid69, blk, SMEM_BYTES>>>(
            69, 1536, s, w2t, 1536, b2, out, 69);
    }
}

// round 6
// speedup vs baseline: 9.0267x; 1.2153x over previous
#include <cuda_runtime.h>
#include <cuda_fp16.h>
#include <cstdint>

// ---------------------------------------------------------------------------
// GraphDecoder decode-step — fp16 mma.sync (m16n8k16), ldmatrix fragments,
// SW128-swizzled smem, 3-stage cp.async pipeline.
// (tcgen05 is not compilable under this harness: PTX virtual target is
//  compute_103 without the 'a' feature set — verified R4.)
//
//   K1: hist = relu([znode | boh8]        @ wbond)  Kpad=576
//   K3: h_t  = relu([gvec | xnode | ctx]  @ topo)   K=1152
//   K4: h_a  = relu([gvec | xnode | ctx]  @ atom)   K=1152
//   K2: cur  = relu([hist | aoh]          @ rbond)  K=576
//   K5: h_b  = relu([gvec|cur|znode|ctx]  @ bond)   K=1664
//   K6: out  = [h_t|h_a|h_b] @ W2t + b2             K=1536, N=69 (f32 out)
//
// Tile: BM=128 BN=128 BK=64, 256 thr, 8 warps x (64x32) warp tiles.
// ---------------------------------------------------------------------------

#define M_ROWS 32768
#define BM 128
#define BN 128
#define BK 64
#define ATILE_B (BM * BK * 2)            // 16384 B (128 rows x 128 B)
#define STAGE_B (2 * ATILE_B)            // A + B = 32768 B
#define NSTAGE 3
#define SMEM_BYTES (NSTAGE * STAGE_B)    // 98304 B

struct SegH { const __half* ptr; int width; };
struct SegsH { SegH s[4]; };

// ----- fp16 scratch -----
__device__ __half g_gvec_h [(size_t)M_ROWS * 512];
__device__ __half g_xnode_h[(size_t)M_ROWS * 512];
__device__ __half g_znode_h[(size_t)M_ROWS * 512];
__device__ __half g_ctx_h  [(size_t)M_ROWS * 128];
__device__ __half g_aoh_h  [(size_t)M_ROWS * 64];
__device__ __half g_boh_h  [(size_t)M_ROWS * 8];
__device__ __half g_hist_h [(size_t)M_ROWS * 512];
__device__ __half g_cur_h  [(size_t)M_ROWS * 512];
__device__ __half g_ht_h   [(size_t)M_ROWS * 512];
__device__ __half g_ha_h   [(size_t)M_ROWS * 512];
__device__ __half g_hb_h   [(size_t)M_ROWS * 512];
__device__ __half g_wt_topo [512 * 1152];
__device__ __half g_wt_atom [512 * 1152];
__device__ __half g_wt_bond [512 * 1664];
__device__ __half g_wt_rbond[512 * 576];
__device__ __half g_wt_wbond[512 * 576];     // Kpad=576 (K=520 zero-padded)
__device__ __half g_w2t     [128 * 1536];    // rows 69..127 zero
__device__ float  g_b2[72];

// ---------------------------------------------------------------------------
// Pre-pass kernels
// ---------------------------------------------------------------------------
__global__ void cvt_f2h(const float* __restrict__ in, __half* __restrict__ out, int n)
{
    int i = (blockIdx.x * blockDim.x + threadIdx.x) * 4;
    if (i + 3 < n) {
        float4 v = *reinterpret_cast<const float4*>(in + i);
        *reinterpret_cast<__half2*>(out + i)     = __floats2half2_rn(v.x, v.y);
        *reinterpret_cast<__half2*>(out + i + 2) = __floats2half2_rn(v.z, v.w);
    } else {
        for (; i < n; ++i) out[i] = __float2half_rn(in[i]);
    }
}

__global__ void gather_ctx(const float* __restrict__ src, const int* __restrict__ idx,
                           __half* __restrict__ out)
{
    int i = blockIdx.x * blockDim.x + threadIdx.x;
    int m = i >> 5;
    int j = (i & 31) * 4;
    float4 v = *reinterpret_cast<const float4*>(src + (size_t)idx[m] * 128 + j);
    __half* o = out + (size_t)m * 128 + j;
    *reinterpret_cast<__half2*>(o)     = __floats2half2_rn(v.x, v.y);
    *reinterpret_cast<__half2*>(o + 2) = __floats2half2_rn(v.z, v.w);
}

__global__ void pad_boh(const float* __restrict__ in, __half* __restrict__ out)
{
    int i = blockIdx.x * blockDim.x + threadIdx.x;
    int m = i >> 3;
    int j = i & 7;
    out[i] = (j < 4) ? __float2half_rn(in[m * 4 + j]) : __half(0.0f);
}

// w [Kin][N] f32 -> wt [N][Kpad] fp16, smem-tiled (coalesced both sides)
__global__ void transpose_w(const float* __restrict__ w, __half* __restrict__ wt,
                            int Kin, int Kpad, int N)
{
    __shared__ float t[32][33];
    int kb = blockIdx.x * 32, nb = blockIdx.y * 32;
    int x = threadIdx.x, y = threadIdx.y;  // (32, 8)
#pragma unroll
    for (int dy = 0; dy < 32; dy += 8) {
        int k = kb + y + dy, n = nb + x;
        t[y + dy][x] = (k < Kin && n < N) ? w[(size_t)k * N + n] : 0.0f;
    }
    __syncthreads();
#pragma unroll
    for (int dy = 0; dy < 32; dy += 8) {
        int n = nb + y + dy, k = kb + x;
        if (n < N && k < Kpad) wt[(size_t)n * Kpad + k] = __float2half_rn(t[x][y + dy]);
    }
}

__global__ void build_w2t(const float* __restrict__ tw2, const float* __restrict__ tb2,
                          const float* __restrict__ aw2, const float* __restrict__ ab2,
                          const float* __restrict__ bw2, const float* __restrict__ bb2)
{
    int i = blockIdx.x * blockDim.x + threadIdx.x;
    if (i < 128 * 1536) {
        int n = i / 1536, k = i - n * 1536;
        float v = 0.0f;
        if (n == 0) {
            if (k < 512) v = tw2[k];
        } else if (n < 65) {
            if (k >= 512 && k < 1024) v = aw2[(k - 512) * 64 + (n - 1)];
        } else if (n < 69) {
            if (k >= 1024) v = bw2[(k - 1024) * 4 + (n - 65)];
        }
        g_w2t[i] = __float2half_rn(v);
    }
    if (i < 72) {
        float b = 0.0f;
        if (i == 0)      b = tb2[0];
        else if (i < 65) b = ab2[i - 1];
        else if (i < 69) b = bb2[i - 65];
        g_b2[i] = b;
    }
}

// ---------------------------------------------------------------------------
__device__ __forceinline__ void cp_async16(uint32_t smem_dst, const void* gsrc, int src_bytes)
{
    asm volatile("cp.async.cg.shared.global [%0], [%1], 16, %2;\n"
                 :: "r"(smem_dst), "l"(gsrc), "r"(src_bytes));
}
__device__ __forceinline__ void mma_f16(float* c, const uint32_t* a, const uint32_t* b)
{
    asm volatile(
        "mma.sync.aligned.m16n8k16.row.col.f32.f16.f16.f32 "
        "{%0,%1,%2,%3}, {%4,%5,%6,%7}, {%8,%9}, {%0,%1,%2,%3};"
        : "+f"(c[0]), "+f"(c[1]), "+f"(c[2]), "+f"(c[3])
        : "r"(a[0]), "r"(a[1]), "r"(a[2]), "r"(a[3]), "r"(b[0]), "r"(b[1]));
}
__device__ __forceinline__ void ldsm_x4(uint32_t& r0, uint32_t& r1, uint32_t& r2,
                                        uint32_t& r3, uint32_t addr)
{
    asm volatile("ldmatrix.sync.aligned.m8n8.x4.shared.b16 {%0,%1,%2,%3}, [%4];"
                 : "=r"(r0), "=r"(r1), "=r"(r2), "=r"(r3) : "r"(addr));
}
// SW128 swizzle of (row*128 + kbyte), kbyte < 128:
//   sw = row*128 + (kbyte ^ ((row & 7) * 16))
__device__ __forceinline__ uint32_t swz(uint32_t row, uint32_t kbyte)
{
    return row * 128u + (kbyte ^ ((row & 7u) * 16u));
}

// ---------------------------------------------------------------------------
// Segmented-A fp16 GEMM.  C = act(A_concat[M,K] @ Bt[N,Kpad]^T + bias).
// Kpad multiple of 64. Segment widths multiples of 8.
// ---------------------------------------------------------------------------
template <int NSEG, bool RELU, bool OUTH>
__global__ __launch_bounds__(256, 2)
void mma_h(int N, int Kpad, SegsH segs,
           const __half* __restrict__ Bt, int ldb,
           const float* __restrict__ bias,
           void* __restrict__ Cv, int ldc)
{
    extern __shared__ char sm[];
    const uint32_t sbase = (uint32_t)__cvta_generic_to_shared(sm);

    const int bn   = blockIdx.x * BN;
    const int bm   = blockIdx.y * BM;
    const int tid  = threadIdx.x;
    const int lane = tid & 31;
    const int warp = tid >> 5;
    const int wm   = warp >> 2;   // 0..1 -> m offset wm*64
    const int wn   = warp & 3;    // 0..3 -> n offset wn*32

    // loader mapping: row band + fixed 16B chunk column
    const int arow = tid >> 3;    // 0..31 (+32 per pass)
    const int ac8  = tid & 7;     // chunk (8 halfs = 16 B)

    const int nk = Kpad / BK;

    // ldmatrix per-lane row/base precompute
    // A x4: matrices (m0..7,k0)(m8..15,k0)(m0..7,k8)(m8..15,k8)
    const uint32_t a_row_l = (lane & 7) + ((lane >> 3) & 1) * 8;   // + mt*16 + wm*64
    const uint32_t a_kx    = ((lane >> 4) & 1) * 16;               // +16B for k8 half
    // B x4: matrices (n0..7,k0)(n0..7,k8)(n8..15,k0)(n8..15,k8)
    const uint32_t b_row_l = (lane & 7) + ((lane >> 4) & 1) * 8;   // + ntp*16 + wn*32
    const uint32_t b_kx    = ((lane >> 3) & 1) * 16;

    float acc[4][4][4];
#pragma unroll
    for (int mt = 0; mt < 4; ++mt)
#pragma unroll
        for (int nt = 0; nt < 4; ++nt)
#pragma unroll
            for (int i = 0; i < 4; ++i) acc[mt][nt][i] = 0.0f;

    auto load_tile = [&](int kt, int buf) {
        const uint32_t Aoff = sbase + buf * STAGE_B;
        const uint32_t Boff = Aoff + ATILE_B;
        const int k0 = kt * BK;
        // A: resolve segment for this thread's fixed column
        const int col = k0 + ac8 * 8;
        const __half* sptr = nullptr;
        int swid = 0, cloc = 0;
        bool valid = false;
        int cc = col;
#pragma unroll
        for (int s = 0; s < NSEG; ++s) {
            if (cc >= 0 && cc < segs.s[s].width) {
                sptr = segs.s[s].ptr; swid = segs.s[s].width; cloc = cc; valid = true;
            }
            cc -= segs.s[s].width;
        }
#pragma unroll
        for (int p = 0; p < 4; ++p) {
            const uint32_t row = arow + 32 * p;
            const void* src = valid
                ? (const void*)(sptr + (size_t)(bm + row) * swid + cloc)
                : (const void*)bias;
            cp_async16(Aoff + swz(row, ac8 * 16), src, valid ? 16 : 0);
        }
#pragma unroll
        for (int p = 0; p < 4; ++p) {
            const uint32_t row = arow + 32 * p;
            const void* src = Bt + (size_t)(bn + row) * ldb + k0 + ac8 * 8;
            cp_async16(Boff + swz(row, ac8 * 16), src, 16);
        }
        asm volatile("cp.async.commit_group;\n" ::);
    };

    // ---- 3-stage pipeline ----
    load_tile(0, 0);
    if (nk > 1) load_tile(1, 1);

    for (int kt = 0; kt < nk; ++kt) {
        const int buf = kt % NSTAGE;
        if (kt + 1 < nk) asm volatile("cp.async.wait_group 1;\n" ::);
        else             asm volatile("cp.async.wait_group 0;\n" ::);
        __syncthreads();
        if (kt + 2 < nk) load_tile(kt + 2, (kt + 2) % NSTAGE);

        const uint32_t Aoff = sbase + buf * STAGE_B;
        const uint32_t Boff = Aoff + ATILE_B;

#pragma unroll
        for (int s = 0; s < BK / 16; ++s) {        // 4 k16 steps
            const uint32_t ka = s * 32 + a_kx;     // byte offset of this step
            const uint32_t kb = s * 32 + b_kx;
            uint32_t a[4][4], b[2][4];
#pragma unroll
            for (int mt = 0; mt < 4; ++mt) {
                const uint32_t row = wm * 64 + mt * 16 + a_row_l;
                ldsm_x4(a[mt][0], a[mt][1], a[mt][2], a[mt][3], Aoff + swz(row, ka));
            }
#pragma unroll
            for (int np = 0; np < 2; ++np) {
                const uint32_t row = wn * 32 + np * 16 + b_row_l;
                ldsm_x4(b[np][0], b[np][1], b[np][2], b[np][3], Boff + swz(row, kb));
            }
#pragma unroll
            for (int mt = 0; mt < 4; ++mt)
#pragma unroll
                for (int nt = 0; nt < 4; ++nt)
                    mma_f16(acc[mt][nt], a[mt], &b[nt >> 1][(nt & 1) * 2]);
        }
        __syncthreads();
    }

    // ---- epilogue ----
#pragma unroll
    for (int mt = 0; mt < 4; ++mt) {
        const int r0 = bm + wm * 64 + mt * 16 + (lane >> 2);
#pragma unroll
        for (int nt = 0; nt < 4; ++nt) {
            const int c0 = bn + wn * 32 + nt * 8 + (lane & 3) * 2;
            float bv0 = (c0     < N) ? bias[c0]     : 0.0f;
            float bv1 = (c0 + 1 < N) ? bias[c0 + 1] : 0.0f;
            float v00 = acc[mt][nt][0] + bv0;
            float v01 = acc[mt][nt][1] + bv1;
            float v10 = acc[mt][nt][2] + bv0;
            float v11 = acc[mt][nt][3] + bv1;
            if (RELU) {
                v00 = fmaxf(v00, 0.0f); v01 = fmaxf(v01, 0.0f);
                v10 = fmaxf(v10, 0.0f); v11 = fmaxf(v11, 0.0f);
            }
            if (OUTH) {
                __half* C = (__half*)Cv;
                *reinterpret_cast<__half2*>(C + (size_t)r0 * ldc + c0)
                    = __floats2half2_rn(v00, v01);
                *reinterpret_cast<__half2*>(C + (size_t)(r0 + 8) * ldc + c0)
                    = __floats2half2_rn(v10, v11);
            } else {
                float* C = (float*)Cv;
                if (c0 < N) {
                    C[(size_t)r0 * ldc + c0]       = v00;
                    C[(size_t)(r0 + 8) * ldc + c0] = v10;
                }
                if (c0 + 1 < N) {
                    C[(size_t)r0 * ldc + c0 + 1]       = v01;
                    C[(size_t)(r0 + 8) * ldc + c0 + 1] = v11;
                }
            }
        }
    }
}

// ---------------------------------------------------------------------------
extern "C" void kernel_launch(void* const* d_in, const int* in_sizes, int n_in,
                              void* d_out, int out_size)
{
    (void)in_sizes; (void)n_in; (void)out_size;

    const float* src_graph_vecs = (const float*)d_in[0];
    const float* gvec           = (const float*)d_in[1];
    const float* xnode          = (const float*)d_in[2];
    const float* znode          = (const float*)d_in[3];
    const float* atom_onehot    = (const float*)d_in[4];
    const float* bond_onehot    = (const float*)d_in[5];
    const float* topo_w1        = (const float*)d_in[6];
    const float* topo_b1        = (const float*)d_in[7];
    const float* topo_w2        = (const float*)d_in[8];
    const float* topo_b2        = (const float*)d_in[9];
    const float* atom_w1        = (const float*)d_in[10];
    const float* atom_b1        = (const float*)d_in[11];
    const float* atom_w2        = (const float*)d_in[12];
    const float* atom_b2        = (const float*)d_in[13];
    const float* bond_w1        = (const float*)d_in[14];
    const float* bond_b1        = (const float*)d_in[15];
    const float* bond_w2        = (const float*)d_in[16];
    const float* bond_b2        = (const float*)d_in[17];
    const float* rbond_w        = (const float*)d_in[18];
    const float* rbond_b        = (const float*)d_in[19];
    const float* wbond_w        = (const float*)d_in[20];
    const float* wbond_b        = (const float*)d_in[21];
    const int*   batch_idx      = (const int*)d_in[22];
    float*       out            = (float*)d_out;

    __half *gvh, *xnh, *znh, *ctxh, *aohh, *bohh;
    __half *histh, *curh, *hth, *hah, *hbh;
    __half *wtT, *wtA, *wtB, *wtR, *wtW, *w2t;
    float  *b2;
    cudaGetSymbolAddress((void**)&gvh,   g_gvec_h);
    cudaGetSymbolAddress((void**)&xnh,   g_xnode_h);
    cudaGetSymbolAddress((void**)&znh,   g_znode_h);
    cudaGetSymbolAddress((void**)&ctxh,  g_ctx_h);
    cudaGetSymbolAddress((void**)&aohh,  g_aoh_h);
    cudaGetSymbolAddress((void**)&bohh,  g_boh_h);
    cudaGetSymbolAddress((void**)&histh, g_hist_h);
    cudaGetSymbolAddress((void**)&curh,  g_cur_h);
    cudaGetSymbolAddress((void**)&hth,   g_ht_h);
    cudaGetSymbolAddress((void**)&hah,   g_ha_h);
    cudaGetSymbolAddress((void**)&hbh,   g_hb_h);
    cudaGetSymbolAddress((void**)&wtT,   g_wt_topo);
    cudaGetSymbolAddress((void**)&wtA,   g_wt_atom);
    cudaGetSymbolAddress((void**)&wtB,   g_wt_bond);
    cudaGetSymbolAddress((void**)&wtR,   g_wt_rbond);
    cudaGetSymbolAddress((void**)&wtW,   g_wt_wbond);
    cudaGetSymbolAddress((void**)&w2t,   g_w2t);
    cudaGetSymbolAddress((void**)&b2,    g_b2);

    cudaFuncSetAttribute(mma_h<2, true, true>,
        cudaFuncAttributeMaxDynamicSharedMemorySize, SMEM_BYTES);
    cudaFuncSetAttribute(mma_h<3, true, true>,
        cudaFuncAttributeMaxDynamicSharedMemorySize, SMEM_BYTES);
    cudaFuncSetAttribute(mma_h<4, true, true>,
        cudaFuncAttributeMaxDynamicSharedMemorySize, SMEM_BYTES);
    cudaFuncSetAttribute(mma_h<3, false, false>,
        cudaFuncAttributeMaxDynamicSharedMemorySize, SMEM_BYTES);

    // ---- pre-pass ----
    const int M = M_ROWS;
    cvt_f2h<<<(M * 512 / 4 + 255) / 256, 256>>>(gvec,  gvh, M * 512);
    cvt_f2h<<<(M * 512 / 4 + 255) / 256, 256>>>(xnode, xnh, M * 512);
    cvt_f2h<<<(M * 512 / 4 + 255) / 256, 256>>>(znode, znh, M * 512);
    cvt_f2h<<<(M * 64  / 4 + 255) / 256, 256>>>(atom_onehot, aohh, M * 64);
    gather_ctx<<<(M * 32 + 255) / 256, 256>>>(src_graph_vecs, batch_idx, ctxh);
    pad_boh<<<(M * 8 + 255) / 256, 256>>>(bond_onehot, bohh);
    {
        dim3 tb(32, 8);
        transpose_w<<<dim3(1152 / 32, 512 / 32), tb>>>(topo_w1, wtT, 1152, 1152, 512);
        transpose_w<<<dim3(1152 / 32, 512 / 32), tb>>>(atom_w1, wtA, 1152, 1152, 512);
        transpose_w<<<dim3(1664 / 32, 512 / 32), tb>>>(bond_w1, wtB, 1664, 1664, 512);
        transpose_w<<<dim3(576  / 32, 512 / 32), tb>>>(rbond_w, wtR, 576, 576, 512);
        transpose_w<<<dim3(576  / 32, 512 / 32), tb>>>(wbond_w, wtW, 516, 576, 512);
    }
    build_w2t<<<(128 * 1536 + 255) / 256, 256>>>(topo_w2, topo_b2, atom_w2, atom_b2,
                                                 bond_w2, bond_b2);

    const dim3 blk(256);
    const dim3 grid512(512 / BN, M / BM);   // (4, 256)
    const dim3 grid69(1, M / BM);           // (1, 256)

    // K1: hist = relu([znode | boh8] @ wbond), Kpad=576
    {
        SegsH s; s.s[0] = {znh, 512}; s.s[1] = {bohh, 8};
        s.s[2] = {nullptr, 0}; s.s[3] = {nullptr, 0};
        mma_h<2, true, true><<<grid512, blk, SMEM_BYTES>>>(
            512, 576, s, wtW, 576, wbond_b, histh, 512);
    }
    // K3: h_t = relu([gvec | xnode | ctx] @ topo), K=1152
    {
        SegsH s; s.s[0] = {gvh, 512}; s.s[1] = {xnh, 512};
        s.s[2] = {ctxh, 128}; s.s[3] = {nullptr, 0};
        mma_h<3, true, true><<<grid512, blk, SMEM_BYTES>>>(
            512, 1152, s, wtT, 1152, topo_b1, hth, 512);
    }
    // K4: h_a = relu([gvec | xnode | ctx] @ atom), K=1152
    {
        SegsH s; s.s[0] = {gvh, 512}; s.s[1] = {xnh, 512};
        s.s[2] = {ctxh, 128}; s.s[3] = {nullptr, 0};
        mma_h<3, true, true><<<grid512, blk, SMEM_BYTES>>>(
            512, 1152, s, wtA, 1152, atom_b1, hah, 512);
    }
    // K2: cur = relu([hist | aoh] @ rbond), K=576
    {
        SegsH s; s.s[0] = {histh, 512}; s.s[1] = {aohh, 64};
        s.s[2] = {nullptr, 0}; s.s[3] = {nullptr, 0};
        mma_h<2, true, true><<<grid512, blk, SMEM_BYTES>>>(
            512, 576, s, wtR, 576, rbond_b, curh, 512);
    }
    // K5: h_b = relu([gvec | cur | znode | ctx] @ bond), K=1664
    {
        SegsH s; s.s[0] = {gvh, 512}; s.s[1] = {curh, 512};
        s.s[2] = {znh, 512}; s.s[3] = {ctxh, 128};
        mma_h<4, true, true><<<grid512, blk, SMEM_BYTES>>>(
            512, 1664, s, wtB, 1664, bond_b1, hbh, 512);
    }
    // K6: out = [h_t | h_a | h_b] @ W2t + b2, K=1536, N=69 (f32)
    {
        SegsH s; s.s[0] = {hth, 512}; s.s[1] = {hah, 512};
        s.s[2] = {hbh, 512}; s.s[3] = {nullptr, 0};
        mma_h<3, false, false><<<grid69, blk, SMEM_BYTES>>>(
            69, 1536, s, w2t, 1536, b2, out, 69);
    }
}

// round 7
// speedup vs baseline: 9.0746x; 1.0053x over previous
#include <cuda_runtime.h>
#include <cuda_fp16.h>
#include <cstdint>

// ---------------------------------------------------------------------------
// GraphDecoder decode-step — fp16 mma.sync (m16n8k16), ldmatrix + SW128 smem,
// 3-stage cp.async pipeline. (tcgen05 not compilable: harness PTX target is
// compute_103 without the 'a' feature set — verified R4.)
//
//   P : fused prepass (fp16 rounding + ctx gather), boh pad, transposes,
//       W2 block-diag assembly, bias concat
//   K1: hist = relu([znode | boh8]        @ wbond)   Kpad=576
//   KF: hta  = relu([gvec | xnode | ctx]  @ [topo|atom]) K=1152, N=1024 (fused)
//   K2: cur  = relu([hist | aoh]          @ rbond)   K=576
//   K5: h_b  = relu([gvec|cur|znode|ctx]  @ bond)    K=1664
//   K6: out  = [hta | h_b] @ W2t + b2                K=1536, N=69 (f32 out)
// ---------------------------------------------------------------------------

#define M_ROWS 32768
#define BM 128
#define BN 128
#define BK 64
#define ATILE_B (BM * BK * 2)            // 16384 B
#define STAGE_B (2 * ATILE_B)            // 32768 B
#define NSTAGE 3
#define SMEM_BYTES (NSTAGE * STAGE_B)    // 98304 B

struct SegH { const __half* ptr; int width; };
struct SegsH { SegH s[4]; };

// ----- fp16 scratch -----
__device__ __half g_gvec_h [(size_t)M_ROWS * 512];
__device__ __half g_xnode_h[(size_t)M_ROWS * 512];
__device__ __half g_znode_h[(size_t)M_ROWS * 512];
__device__ __half g_ctx_h  [(size_t)M_ROWS * 128];
__device__ __half g_aoh_h  [(size_t)M_ROWS * 64];
__device__ __half g_boh_h  [(size_t)M_ROWS * 8];
__device__ __half g_hist_h [(size_t)M_ROWS * 512];
__device__ __half g_cur_h  [(size_t)M_ROWS * 512];
__device__ __half g_hta_h  [(size_t)M_ROWS * 1024];   // fused topo|atom hidden
__device__ __half g_hb_h   [(size_t)M_ROWS * 512];
__device__ __half g_wt_ta   [1024 * 1152];             // [topo^T ; atom^T]
__device__ __half g_wt_bond [512 * 1664];
__device__ __half g_wt_rbond[512 * 576];
__device__ __half g_wt_wbond[512 * 576];               // Kpad=576 (K=520 padded)
__device__ __half g_w2t     [128 * 1536];              // rows 69..127 zero
__device__ float  g_b_ta[1024];
__device__ float  g_b2[72];

// ---------------------------------------------------------------------------
// Pre-pass
// ---------------------------------------------------------------------------
// One grid-stride kernel over float4 units: gvec | xnode | znode | aoh | ctx
__global__ void prepass_main(const float* __restrict__ gvec,
                             const float* __restrict__ xnode,
                             const float* __restrict__ znode,
                             const float* __restrict__ aoh,
                             const float* __restrict__ src,
                             const int* __restrict__ idx,
                             __half* __restrict__ gvh, __half* __restrict__ xnh,
                             __half* __restrict__ znh, __half* __restrict__ aohh,
                             __half* __restrict__ ctxh)
{
    const int n512 = M_ROWS * 128;          // float4 units per 512-wide tensor
    const int nA   = M_ROWS * 16;
    const int nC   = M_ROWS * 32;
    int i = blockIdx.x * blockDim.x + threadIdx.x;
    if (i >= 3 * n512 + nA + nC) return;

    const float* in;
    __half* out;
    int j;
    if (i < n512)            { in = gvec;  out = gvh;  j = i; }
    else if (i < 2 * n512)   { in = xnode; out = xnh;  j = i - n512; }
    else if (i < 3 * n512)   { in = znode; out = znh;  j = i - 2 * n512; }
    else if (i < 3 * n512 + nA) { in = aoh; out = aohh; j = i - 3 * n512; }
    else {
        j = i - 3 * n512 - nA;
        int m = j >> 5;
        int c = (j & 31) * 4;
        float4 v = *reinterpret_cast<const float4*>(src + (size_t)idx[m] * 128 + c);
        __half* o = ctxh + (size_t)m * 128 + c;
        *reinterpret_cast<__half2*>(o)     = __floats2half2_rn(v.x, v.y);
        *reinterpret_cast<__half2*>(o + 2) = __floats2half2_rn(v.z, v.w);
        return;
    }
    float4 v = *reinterpret_cast<const float4*>(in + (size_t)j * 4);
    *reinterpret_cast<__half2*>(out + (size_t)j * 4)     = __floats2half2_rn(v.x, v.y);
    *reinterpret_cast<__half2*>(out + (size_t)j * 4 + 2) = __floats2half2_rn(v.z, v.w);
}

__global__ void pad_boh(const float* __restrict__ in, __half* __restrict__ out)
{
    int i = blockIdx.x * blockDim.x + threadIdx.x;
    int m = i >> 3;
    int j = i & 7;
    out[i] = (j < 4) ? __float2half_rn(in[m * 4 + j]) : __half(0.0f);
}

// w [Kin][N] f32 -> wt [N][Kpad] fp16, smem-tiled (coalesced both sides)
__global__ void transpose_w(const float* __restrict__ w, __half* __restrict__ wt,
                            int Kin, int Kpad, int N)
{
    __shared__ float t[32][33];
    int kb = blockIdx.x * 32, nb = blockIdx.y * 32;
    int x = threadIdx.x, y = threadIdx.y;  // (32, 8)
#pragma unroll
    for (int dy = 0; dy < 32; dy += 8) {
        int k = kb + y + dy, n = nb + x;
        t[y + dy][x] = (k < Kin && n < N) ? w[(size_t)k * N + n] : 0.0f;
    }
    __syncthreads();
#pragma unroll
    for (int dy = 0; dy < 32; dy += 8) {
        int n = nb + y + dy, k = kb + x;
        if (n < N && k < Kpad) wt[(size_t)n * Kpad + k] = __float2half_rn(t[x][y + dy]);
    }
}

__global__ void build_w2t(const float* __restrict__ tw2, const float* __restrict__ tb2,
                          const float* __restrict__ aw2, const float* __restrict__ ab2,
                          const float* __restrict__ bw2, const float* __restrict__ bb2,
                          const float* __restrict__ tb1, const float* __restrict__ ab1)
{
    int i = blockIdx.x * blockDim.x + threadIdx.x;
    if (i < 128 * 1536) {
        int n = i / 1536, k = i - n * 1536;
        float v = 0.0f;
        if (n == 0) {
            if (k < 512) v = tw2[k];
        } else if (n < 65) {
            if (k >= 512 && k < 1024) v = aw2[(k - 512) * 64 + (n - 1)];
        } else if (n < 69) {
            if (k >= 1024) v = bw2[(k - 1024) * 4 + (n - 65)];
        }
        g_w2t[i] = __float2half_rn(v);
    }
    if (i < 72) {
        float b = 0.0f;
        if (i == 0)      b = tb2[0];
        else if (i < 65) b = ab2[i - 1];
        else if (i < 69) b = bb2[i - 65];
        g_b2[i] = b;
    }
    if (i < 1024) g_b_ta[i] = (i < 512) ? tb1[i] : ab1[i - 512];
}

// ---------------------------------------------------------------------------
__device__ __forceinline__ void cp_async16(uint32_t smem_dst, const void* gsrc, int src_bytes)
{
    asm volatile("cp.async.cg.shared.global [%0], [%1], 16, %2;\n"
                 :: "r"(smem_dst), "l"(gsrc), "r"(src_bytes));
}
__device__ __forceinline__ void mma_f16(float* c, const uint32_t* a, const uint32_t* b)
{
    asm volatile(
        "mma.sync.aligned.m16n8k16.row.col.f32.f16.f16.f32 "
        "{%0,%1,%2,%3}, {%4,%5,%6,%7}, {%8,%9}, {%0,%1,%2,%3};"
        : "+f"(c[0]), "+f"(c[1]), "+f"(c[2]), "+f"(c[3])
        : "r"(a[0]), "r"(a[1]), "r"(a[2]), "r"(a[3]), "r"(b[0]), "r"(b[1]));
}
__device__ __forceinline__ void ldsm_x4(uint32_t& r0, uint32_t& r1, uint32_t& r2,
                                        uint32_t& r3, uint32_t addr)
{
    asm volatile("ldmatrix.sync.aligned.m8n8.x4.shared.b16 {%0,%1,%2,%3}, [%4];"
                 : "=r"(r0), "=r"(r1), "=r"(r2), "=r"(r3) : "r"(addr));
}
__device__ __forceinline__ uint32_t swz(uint32_t row, uint32_t kbyte)
{
    return row * 128u + (kbyte ^ ((row & 7u) * 16u));
}

// ---------------------------------------------------------------------------
// Segmented-A fp16 GEMM.  C = act(A_concat[M,K] @ Bt[N,Kpad]^T + bias).
// Kpad multiple of 64; segment widths multiples of 8.
// Warps whose 32-col n-range lies beyond round8(N) skip all MMA work.
// ---------------------------------------------------------------------------
template <int NSEG, bool RELU, bool OUTH>
__global__ __launch_bounds__(256, 2)
void mma_h(int N, int Kpad, SegsH segs,
           const __half* __restrict__ Bt, int ldb,
           const float* __restrict__ bias,
           void* __restrict__ Cv, int ldc)
{
    extern __shared__ char sm[];
    const uint32_t sbase = (uint32_t)__cvta_generic_to_shared(sm);

    const int bn   = blockIdx.x * BN;
    const int bm   = blockIdx.y * BM;
    const int tid  = threadIdx.x;
    const int lane = tid & 31;
    const int warp = tid >> 5;
    const int wm   = warp >> 2;
    const int wn   = warp & 3;

    const int arow = tid >> 3;
    const int ac8  = tid & 7;

    const int nk = Kpad / BK;
    const bool wact = (bn + wn * 32) < ((N + 7) & ~7);

    const uint32_t a_row_l = (lane & 7) + ((lane >> 3) & 1) * 8;
    const uint32_t a_kx    = ((lane >> 4) & 1) * 16;
    const uint32_t b_row_l = (lane & 7) + ((lane >> 4) & 1) * 8;
    const uint32_t b_kx    = ((lane >> 3) & 1) * 16;

    float acc[4][4][4];
#pragma unroll
    for (int mt = 0; mt < 4; ++mt)
#pragma unroll
        for (int nt = 0; nt < 4; ++nt)
#pragma unroll
            for (int i = 0; i < 4; ++i) acc[mt][nt][i] = 0.0f;

    auto load_tile = [&](int kt, int buf) {
        const uint32_t Aoff = sbase + buf * STAGE_B;
        const uint32_t Boff = Aoff + ATILE_B;
        const int k0 = kt * BK;
        const int col = k0 + ac8 * 8;
        const __half* sptr = nullptr;
        int swid = 0, cloc = 0;
        bool valid = false;
        int cc = col;
#pragma unroll
        for (int s = 0; s < NSEG; ++s) {
            if (cc >= 0 && cc < segs.s[s].width) {
                sptr = segs.s[s].ptr; swid = segs.s[s].width; cloc = cc; valid = true;
            }
            cc -= segs.s[s].width;
        }
#pragma unroll
        for (int p = 0; p < 4; ++p) {
            const uint32_t row = arow + 32 * p;
            const void* src = valid
                ? (const void*)(sptr + (size_t)(bm + row) * swid + cloc)
                : (const void*)bias;
            cp_async16(Aoff + swz(row, ac8 * 16), src, valid ? 16 : 0);
        }
#pragma unroll
        for (int p = 0; p < 4; ++p) {
            const uint32_t row = arow + 32 * p;
            const void* src = Bt + (size_t)(bn + row) * ldb + k0 + ac8 * 8;
            cp_async16(Boff + swz(row, ac8 * 16), src, 16);
        }
        asm volatile("cp.async.commit_group;\n" ::);
    };

    // ---- 3-stage pipeline (prefetch-before-wait) ----
    load_tile(0, 0);
    if (nk > 1) load_tile(1, 1);

    for (int kt = 0; kt < nk; ++kt) {
        const int buf = kt % NSTAGE;
        if (kt + 2 < nk) {
            load_tile(kt + 2, (kt + 2) % NSTAGE);
            asm volatile("cp.async.wait_group 2;\n" ::);
        } else if (kt + 1 < nk) {
            asm volatile("cp.async.wait_group 1;\n" ::);
        } else {
            asm volatile("cp.async.wait_group 0;\n" ::);
        }
        __syncthreads();

        const uint32_t Aoff = sbase + buf * STAGE_B;
        const uint32_t Boff = Aoff + ATILE_B;

        if (wact) {
#pragma unroll
            for (int s = 0; s < BK / 16; ++s) {
                const uint32_t ka = s * 32 + a_kx;
                const uint32_t kb = s * 32 + b_kx;
                uint32_t a[4][4], b[2][4];
#pragma unroll
                for (int mt = 0; mt < 4; ++mt) {
                    const uint32_t row = wm * 64 + mt * 16 + a_row_l;
                    ldsm_x4(a[mt][0], a[mt][1], a[mt][2], a[mt][3], Aoff + swz(row, ka));
                }
#pragma unroll
                for (int np = 0; np < 2; ++np) {
                    const uint32_t row = wn * 32 + np * 16 + b_row_l;
                    ldsm_x4(b[np][0], b[np][1], b[np][2], b[np][3], Boff + swz(row, kb));
                }
#pragma unroll
                for (int mt = 0; mt < 4; ++mt)
#pragma unroll
                    for (int nt = 0; nt < 4; ++nt)
                        mma_f16(acc[mt][nt], a[mt], &b[nt >> 1][(nt & 1) * 2]);
            }
        }
        __syncthreads();
    }

    // ---- epilogue ----
#pragma unroll
    for (int mt = 0; mt < 4; ++mt) {
        const int r0 = bm + wm * 64 + mt * 16 + (lane >> 2);
#pragma unroll
        for (int nt = 0; nt < 4; ++nt) {
            const int c0 = bn + wn * 32 + nt * 8 + (lane & 3) * 2;
            float bv0 = (c0     < N) ? bias[c0]     : 0.0f;
            float bv1 = (c0 + 1 < N) ? bias[c0 + 1] : 0.0f;
            float v00 = acc[mt][nt][0] + bv0;
            float v01 = acc[mt][nt][1] + bv1;
            float v10 = acc[mt][nt][2] + bv0;
            float v11 = acc[mt][nt][3] + bv1;
            if (RELU) {
                v00 = fmaxf(v00, 0.0f); v01 = fmaxf(v01, 0.0f);
                v10 = fmaxf(v10, 0.0f); v11 = fmaxf(v11, 0.0f);
            }
            if (OUTH) {
                __half* C = (__half*)Cv;
                *reinterpret_cast<__half2*>(C + (size_t)r0 * ldc + c0)
                    = __floats2half2_rn(v00, v01);
                *reinterpret_cast<__half2*>(C + (size_t)(r0 + 8) * ldc + c0)
                    = __floats2half2_rn(v10, v11);
            } else {
                float* C = (float*)Cv;
                if (c0 < N) {
                    C[(size_t)r0 * ldc + c0]       = v00;
                    C[(size_t)(r0 + 8) * ldc + c0] = v10;
                }
                if (c0 + 1 < N) {
                    C[(size_t)r0 * ldc + c0 + 1]       = v01;
                    C[(size_t)(r0 + 8) * ldc + c0 + 1] = v11;
                }
            }
        }
    }
}

// ---------------------------------------------------------------------------
extern "C" void kernel_launch(void* const* d_in, const int* in_sizes, int n_in,
                              void* d_out, int out_size)
{
    (void)in_sizes; (void)n_in; (void)out_size;

    const float* src_graph_vecs = (const float*)d_in[0];
    const float* gvec           = (const float*)d_in[1];
    const float* xnode          = (const float*)d_in[2];
    const float* znode          = (const float*)d_in[3];
    const float* atom_onehot    = (const float*)d_in[4];
    const float* bond_onehot    = (const float*)d_in[5];
    const float* topo_w1        = (const float*)d_in[6];
    const float* topo_b1        = (const float*)d_in[7];
    const float* topo_w2        = (const float*)d_in[8];
    const float* topo_b2        = (const float*)d_in[9];
    const float* atom_w1        = (const float*)d_in[10];
    const float* atom_b1        = (const float*)d_in[11];
    const float* atom_w2        = (const float*)d_in[12];
    const float* atom_b2        = (const float*)d_in[13];
    const float* bond_w1        = (const float*)d_in[14];
    const float* bond_b1        = (const float*)d_in[15];
    const float* bond_w2        = (const float*)d_in[16];
    const float* bond_b2        = (const float*)d_in[17];
    const float* rbond_w        = (const float*)d_in[18];
    const float* rbond_b        = (const float*)d_in[19];
    const float* wbond_w        = (const float*)d_in[20];
    const float* wbond_b        = (const float*)d_in[21];
    const int*   batch_idx      = (const int*)d_in[22];
    float*       out            = (float*)d_out;

    __half *gvh, *xnh, *znh, *ctxh, *aohh, *bohh;
    __half *histh, *curh, *htah, *hbh;
    __half *wtTA, *wtB, *wtR, *wtW, *w2t;
    float  *b2, *bta;
    cudaGetSymbolAddress((void**)&gvh,   g_gvec_h);
    cudaGetSymbolAddress((void**)&xnh,   g_xnode_h);
    cudaGetSymbolAddress((void**)&znh,   g_znode_h);
    cudaGetSymbolAddress((void**)&ctxh,  g_ctx_h);
    cudaGetSymbolAddress((void**)&aohh,  g_aoh_h);
    cudaGetSymbolAddress((void**)&bohh,  g_boh_h);
    cudaGetSymbolAddress((void**)&histh, g_hist_h);
    cudaGetSymbolAddress((void**)&curh,  g_cur_h);
    cudaGetSymbolAddress((void**)&htah,  g_hta_h);
    cudaGetSymbolAddress((void**)&hbh,   g_hb_h);
    cudaGetSymbolAddress((void**)&wtTA,  g_wt_ta);
    cudaGetSymbolAddress((void**)&wtB,   g_wt_bond);
    cudaGetSymbolAddress((void**)&wtR,   g_wt_rbond);
    cudaGetSymbolAddress((void**)&wtW,   g_wt_wbond);
    cudaGetSymbolAddress((void**)&w2t,   g_w2t);
    cudaGetSymbolAddress((void**)&b2,    g_b2);
    cudaGetSymbolAddress((void**)&bta,   g_b_ta);

    cudaFuncSetAttribute(mma_h<2, true, true>,
        cudaFuncAttributeMaxDynamicSharedMemorySize, SMEM_BYTES);
    cudaFuncSetAttribute(mma_h<3, true, true>,
        cudaFuncAttributeMaxDynamicSharedMemorySize, SMEM_BYTES);
    cudaFuncSetAttribute(mma_h<4, true, true>,
        cudaFuncAttributeMaxDynamicSharedMemorySize, SMEM_BYTES);
    cudaFuncSetAttribute(mma_h<2, false, false>,
        cudaFuncAttributeMaxDynamicSharedMemorySize, SMEM_BYTES);

    // ---- pre-pass ----
    const int M = M_ROWS;
    {
        int total = 3 * (M * 128) + M * 16 + M * 32;
        prepass_main<<<(total + 255) / 256, 256>>>(
            gvec, xnode, znode, atom_onehot, src_graph_vecs, batch_idx,
            gvh, xnh, znh, aohh, ctxh);
        pad_boh<<<(M * 8 + 255) / 256, 256>>>(bond_onehot, bohh);
        dim3 tb(32, 8);
        transpose_w<<<dim3(1152 / 32, 512 / 32), tb>>>(topo_w1, wtTA, 1152, 1152, 512);
        transpose_w<<<dim3(1152 / 32, 512 / 32), tb>>>(atom_w1, wtTA + (size_t)512 * 1152,
                                                       1152, 1152, 512);
        transpose_w<<<dim3(1664 / 32, 512 / 32), tb>>>(bond_w1, wtB, 1664, 1664, 512);
        transpose_w<<<dim3(576  / 32, 512 / 32), tb>>>(rbond_w, wtR, 576, 576, 512);
        transpose_w<<<dim3(576  / 32, 512 / 32), tb>>>(wbond_w, wtW, 516, 576, 512);
        build_w2t<<<(128 * 1536 + 255) / 256, 256>>>(topo_w2, topo_b2, atom_w2, atom_b2,
                                                     bond_w2, bond_b2, topo_b1, atom_b1);
    }

    const dim3 blk(256);
    const dim3 grid512(512 / BN, M / BM);    // (4, 256)
    const dim3 grid1024(1024 / BN, M / BM);  // (8, 256)
    const dim3 grid69(1, M / BM);            // (1, 256)

    // K1: hist = relu([znode | boh8] @ wbond), Kpad=576
    {
        SegsH s; s.s[0] = {znh, 512}; s.s[1] = {bohh, 8};
        s.s[2] = {nullptr, 0}; s.s[3] = {nullptr, 0};
        mma_h<2, true, true><<<grid512, blk, SMEM_BYTES>>>(
            512, 576, s, wtW, 576, wbond_b, histh, 512);
    }
    // KF: hta = relu([gvec | xnode | ctx] @ [topo|atom]), K=1152, N=1024
    {
        SegsH s; s.s[0] = {gvh, 512}; s.s[1] = {xnh, 512};
        s.s[2] = {ctxh, 128}; s.s[3] = {nullptr, 0};
        mma_h<3, true, true><<<grid1024, blk, SMEM_BYTES>>>(
            1024, 1152, s, wtTA, 1152, bta, htah, 1024);
    }
    // K2: cur = relu([hist | aoh] @ rbond), K=576
    {
        SegsH s; s.s[0] = {histh, 512}; s.s[1] = {aohh, 64};
        s.s[2] = {nullptr, 0}; s.s[3] = {nullptr, 0};
        mma_h<2, true, true><<<grid512, blk, SMEM_BYTES>>>(
            512, 576, s, wtR, 576, rbond_b, curh, 512);
    }
    // K5: h_b = relu([gvec | cur | znode | ctx] @ bond), K=1664
    {
        SegsH s; s.s[0] = {gvh, 512}; s.s[1] = {curh, 512};
        s.s[2] = {znh, 512}; s.s[3] = {ctxh, 128};
        mma_h<4, true, true><<<grid512, blk, SMEM_BYTES>>>(
            512, 1664, s, wtB, 1664, bond_b1, hbh, 512);
    }
    // K6: out = [hta | h_b] @ W2t + b2, K=1536, N=69 (f32); wn=3 warps idle
    {
        SegsH s; s.s[0] = {htah, 1024}; s.s[1] = {hbh, 512};
        s.s[2] = {nullptr, 0}; s.s[3] = {nullptr, 0};
        mma_h<2, false, false><<<grid69, blk, SMEM_BYTES>>>(
            69, 1536, s, w2t, 1536, b2, out, 69);
    }
}

// round 8
// speedup vs baseline: 9.0865x; 1.0013x over previous
#include <cuda_runtime.h>
#include <cuda_fp16.h>
#include <cstdint>

// ---------------------------------------------------------------------------
// GraphDecoder decode-step — fp16 mma.sync (m16n8k16), ldmatrix + SW128 smem,
// 3-stage cp.async pipeline. (tcgen05 not compilable: harness PTX target is
// compute_103 without the 'a' feature set — verified R4.)
//
//   P : fused prepass (fp16 rounding + ctx gather), boh pad, transposes,
//       W2 block-diag assembly, bias concat
//   K1: hist = relu([znode | boh8]        @ wbond)   Kpad=576
//   KF: hta  = relu([gvec | xnode | ctx]  @ [topo|atom]) K=1152, N=1024 (fused)
//   K2: cur  = relu([hist | aoh]          @ rbond)   K=576
//   K5: h_b  = relu([gvec|cur|znode|ctx]  @ bond)    K=1664
//   K6: out  = [hta | h_b] @ W2t + b2                K=1536, N=69 (f32 out)
// ---------------------------------------------------------------------------

#define M_ROWS 32768
#define BM 128
#define BN 128
#define BK 64
#define ATILE_B (BM * BK * 2)            // 16384 B
#define STAGE_B (2 * ATILE_B)            // 32768 B
#define NSTAGE 3
#define SMEM_BYTES (NSTAGE * STAGE_B)    // 98304 B

struct SegH { const __half* ptr; int width; };
struct SegsH { SegH s[4]; };

// ----- fp16 scratch -----
__device__ __half g_gvec_h [(size_t)M_ROWS * 512];
__device__ __half g_xnode_h[(size_t)M_ROWS * 512];
__device__ __half g_znode_h[(size_t)M_ROWS * 512];
__device__ __half g_ctx_h  [(size_t)M_ROWS * 128];
__device__ __half g_aoh_h  [(size_t)M_ROWS * 64];
__device__ __half g_boh_h  [(size_t)M_ROWS * 8];
__device__ __half g_hist_h [(size_t)M_ROWS * 512];
__device__ __half g_cur_h  [(size_t)M_ROWS * 512];
__device__ __half g_hta_h  [(size_t)M_ROWS * 1024];   // fused topo|atom hidden
__device__ __half g_hb_h   [(size_t)M_ROWS * 512];
__device__ __half g_wt_ta   [1024 * 1152];             // [topo^T ; atom^T]
__device__ __half g_wt_bond [512 * 1664];
__device__ __half g_wt_rbond[512 * 576];
__device__ __half g_wt_wbond[512 * 576];               // Kpad=576 (K=520 padded)
__device__ __half g_w2t     [128 * 1536];              // rows 69..127 zero
__device__ float  g_b_ta[1024];
__device__ float  g_b2[72];

// ---------------------------------------------------------------------------
// Pre-pass
// ---------------------------------------------------------------------------
// One grid-stride kernel over float4 units: gvec | xnode | znode | aoh | ctx
__global__ void prepass_main(const float* __restrict__ gvec,
                             const float* __restrict__ xnode,
                             const float* __restrict__ znode,
                             const float* __restrict__ aoh,
                             const float* __restrict__ src,
                             const int* __restrict__ idx,
                             __half* __restrict__ gvh, __half* __restrict__ xnh,
                             __half* __restrict__ znh, __half* __restrict__ aohh,
                             __half* __restrict__ ctxh)
{
    const int n512 = M_ROWS * 128;          // float4 units per 512-wide tensor
    const int nA   = M_ROWS * 16;
    const int nC   = M_ROWS * 32;
    int i = blockIdx.x * blockDim.x + threadIdx.x;
    if (i >= 3 * n512 + nA + nC) return;

    const float* in;
    __half* out;
    int j;
    if (i < n512)            { in = gvec;  out = gvh;  j = i; }
    else if (i < 2 * n512)   { in = xnode; out = xnh;  j = i - n512; }
    else if (i < 3 * n512)   { in = znode; out = znh;  j = i - 2 * n512; }
    else if (i < 3 * n512 + nA) { in = aoh; out = aohh; j = i - 3 * n512; }
    else {
        j = i - 3 * n512 - nA;
        int m = j >> 5;
        int c = (j & 31) * 4;
        float4 v = *reinterpret_cast<const float4*>(src + (size_t)idx[m] * 128 + c);
        __half* o = ctxh + (size_t)m * 128 + c;
        *reinterpret_cast<__half2*>(o)     = __floats2half2_rn(v.x, v.y);
        *reinterpret_cast<__half2*>(o + 2) = __floats2half2_rn(v.z, v.w);
        return;
    }
    float4 v = *reinterpret_cast<const float4*>(in + (size_t)j * 4);
    *reinterpret_cast<__half2*>(out + (size_t)j * 4)     = __floats2half2_rn(v.x, v.y);
    *reinterpret_cast<__half2*>(out + (size_t)j * 4 + 2) = __floats2half2_rn(v.z, v.w);
}

__global__ void pad_boh(const float* __restrict__ in, __half* __restrict__ out)
{
    int i = blockIdx.x * blockDim.x + threadIdx.x;
    int m = i >> 3;
    int j = i & 7;
    out[i] = (j < 4) ? __float2half_rn(in[m * 4 + j]) : __half(0.0f);
}

// w [Kin][N] f32 -> wt [N][Kpad] fp16, smem-tiled (coalesced both sides)
__global__ void transpose_w(const float* __restrict__ w, __half* __restrict__ wt,
                            int Kin, int Kpad, int N)
{
    __shared__ float t[32][33];
    int kb = blockIdx.x * 32, nb = blockIdx.y * 32;
    int x = threadIdx.x, y = threadIdx.y;  // (32, 8)
#pragma unroll
    for (int dy = 0; dy < 32; dy += 8) {
        int k = kb + y + dy, n = nb + x;
        t[y + dy][x] = (k < Kin && n < N) ? w[(size_t)k * N + n] : 0.0f;
    }
    __syncthreads();
#pragma unroll
    for (int dy = 0; dy < 32; dy += 8) {
        int n = nb + y + dy, k = kb + x;
        if (n < N && k < Kpad) wt[(size_t)n * Kpad + k] = __float2half_rn(t[x][y + dy]);
    }
}

__global__ void build_w2t(const float* __restrict__ tw2, const float* __restrict__ tb2,
                          const float* __restrict__ aw2, const float* __restrict__ ab2,
                          const float* __restrict__ bw2, const float* __restrict__ bb2,
                          const float* __restrict__ tb1, const float* __restrict__ ab1)
{
    int i = blockIdx.x * blockDim.x + threadIdx.x;
    if (i < 128 * 1536) {
        int n = i / 1536, k = i - n * 1536;
        float v = 0.0f;
        if (n == 0) {
            if (k < 512) v = tw2[k];
        } else if (n < 65) {
            if (k >= 512 && k < 1024) v = aw2[(k - 512) * 64 + (n - 1)];
        } else if (n < 69) {
            if (k >= 1024) v = bw2[(k - 1024) * 4 + (n - 65)];
        }
        g_w2t[i] = __float2half_rn(v);
    }
    if (i < 72) {
        float b = 0.0f;
        if (i == 0)      b = tb2[0];
        else if (i < 65) b = ab2[i - 1];
        else if (i < 69) b = bb2[i - 65];
        g_b2[i] = b;
    }
    if (i < 1024) g_b_ta[i] = (i < 512) ? tb1[i] : ab1[i - 512];
}

// ---------------------------------------------------------------------------
__device__ __forceinline__ void cp_async16(uint32_t smem_dst, const void* gsrc, int src_bytes)
{
    asm volatile("cp.async.cg.shared.global [%0], [%1], 16, %2;\n"
                 :: "r"(smem_dst), "l"(gsrc), "r"(src_bytes));
}
__device__ __forceinline__ void mma_f16(float* c, const uint32_t* a, const uint32_t* b)
{
    asm volatile(
        "mma.sync.aligned.m16n8k16.row.col.f32.f16.f16.f32 "
        "{%0,%1,%2,%3}, {%4,%5,%6,%7}, {%8,%9}, {%0,%1,%2,%3};"
        : "+f"(c[0]), "+f"(c[1]), "+f"(c[2]), "+f"(c[3])
        : "r"(a[0]), "r"(a[1]), "r"(a[2]), "r"(a[3]), "r"(b[0]), "r"(b[1]));
}
__device__ __forceinline__ void ldsm_x4(uint32_t& r0, uint32_t& r1, uint32_t& r2,
                                        uint32_t& r3, uint32_t addr)
{
    asm volatile("ldmatrix.sync.aligned.m8n8.x4.shared.b16 {%0,%1,%2,%3}, [%4];"
                 : "=r"(r0), "=r"(r1), "=r"(r2), "=r"(r3) : "r"(addr));
}
__device__ __forceinline__ uint32_t swz(uint32_t row, uint32_t kbyte)
{
    return row * 128u + (kbyte ^ ((row & 7u) * 16u));
}

// ---------------------------------------------------------------------------
// Segmented-A fp16 GEMM.  C = act(A_concat[M,K] @ Bt[N,Kpad]^T + bias).
// Kpad multiple of 64; segment widths multiples of 8.
// Warps whose 32-col n-range lies beyond round8(N) skip all MMA work.
// ---------------------------------------------------------------------------
template <int NSEG, bool RELU, bool OUTH>
__global__ __launch_bounds__(256, 2)
void mma_h(int N, int Kpad, SegsH segs,
           const __half* __restrict__ Bt, int ldb,
           const float* __restrict__ bias,
           void* __restrict__ Cv, int ldc)
{
    extern __shared__ char sm[];
    const uint32_t sbase = (uint32_t)__cvta_generic_to_shared(sm);

    const int bn   = blockIdx.x * BN;
    const int bm   = blockIdx.y * BM;
    const int tid  = threadIdx.x;
    const int lane = tid & 31;
    const int warp = tid >> 5;
    const int wm   = warp >> 2;
    const int wn   = warp & 3;

    const int arow = tid >> 3;
    const int ac8  = tid & 7;

    const int nk = Kpad / BK;
    const bool wact = (bn + wn * 32) < ((N + 7) & ~7);

    const uint32_t a_row_l = (lane & 7) + ((lane >> 3) & 1) * 8;
    const uint32_t a_kx    = ((lane >> 4) & 1) * 16;
    const uint32_t b_row_l = (lane & 7) + ((lane >> 4) & 1) * 8;
    const uint32_t b_kx    = ((lane >> 3) & 1) * 16;

    float acc[4][4][4];
#pragma unroll
    for (int mt = 0; mt < 4; ++mt)
#pragma unroll
        for (int nt = 0; nt < 4; ++nt)
#pragma unroll
            for (int i = 0; i < 4; ++i) acc[mt][nt][i] = 0.0f;

    auto load_tile = [&](int kt, int buf) {
        const uint32_t Aoff = sbase + buf * STAGE_B;
        const uint32_t Boff = Aoff + ATILE_B;
        const int k0 = kt * BK;
        const int col = k0 + ac8 * 8;
        const __half* sptr = nullptr;
        int swid = 0, cloc = 0;
        bool valid = false;
        int cc = col;
#pragma unroll
        for (int s = 0; s < NSEG; ++s) {
            if (cc >= 0 && cc < segs.s[s].width) {
                sptr = segs.s[s].ptr; swid = segs.s[s].width; cloc = cc; valid = true;
            }
            cc -= segs.s[s].width;
        }
#pragma unroll
        for (int p = 0; p < 4; ++p) {
            const uint32_t row = arow + 32 * p;
            const void* src = valid
                ? (const void*)(sptr + (size_t)(bm + row) * swid + cloc)
                : (const void*)bias;
            cp_async16(Aoff + swz(row, ac8 * 16), src, valid ? 16 : 0);
        }
#pragma unroll
        for (int p = 0; p < 4; ++p) {
            const uint32_t row = arow + 32 * p;
            const void* src = Bt + (size_t)(bn + row) * ldb + k0 + ac8 * 8;
            cp_async16(Boff + swz(row, ac8 * 16), src, 16);
        }
        asm volatile("cp.async.commit_group;\n" ::);
    };

    // ---- 3-stage pipeline (prefetch-before-wait) ----
    load_tile(0, 0);
    if (nk > 1) load_tile(1, 1);

    for (int kt = 0; kt < nk; ++kt) {
        const int buf = kt % NSTAGE;
        if (kt + 2 < nk) {
            load_tile(kt + 2, (kt + 2) % NSTAGE);
            asm volatile("cp.async.wait_group 2;\n" ::);
        } else if (kt + 1 < nk) {
            asm volatile("cp.async.wait_group 1;\n" ::);
        } else {
            asm volatile("cp.async.wait_group 0;\n" ::);
        }
        __syncthreads();

        const uint32_t Aoff = sbase + buf * STAGE_B;
        const uint32_t Boff = Aoff + ATILE_B;

        if (wact) {
#pragma unroll
            for (int s = 0; s < BK / 16; ++s) {
                const uint32_t ka = s * 32 + a_kx;
                const uint32_t kb = s * 32 + b_kx;
                uint32_t a[4][4], b[2][4];
#pragma unroll
                for (int mt = 0; mt < 4; ++mt) {
                    const uint32_t row = wm * 64 + mt * 16 + a_row_l;
                    ldsm_x4(a[mt][0], a[mt][1], a[mt][2], a[mt][3], Aoff + swz(row, ka));
                }
#pragma unroll
                for (int np = 0; np < 2; ++np) {
                    const uint32_t row = wn * 32 + np * 16 + b_row_l;
                    ldsm_x4(b[np][0], b[np][1], b[np][2], b[np][3], Boff + swz(row, kb));
                }
#pragma unroll
                for (int mt = 0; mt < 4; ++mt)
#pragma unroll
                    for (int nt = 0; nt < 4; ++nt)
                        mma_f16(acc[mt][nt], a[mt], &b[nt >> 1][(nt & 1) * 2]);
            }
        }
        __syncthreads();
    }

    // ---- epilogue ----
#pragma unroll
    for (int mt = 0; mt < 4; ++mt) {
        const int r0 = bm + wm * 64 + mt * 16 + (lane >> 2);
#pragma unroll
        for (int nt = 0; nt < 4; ++nt) {
            const int c0 = bn + wn * 32 + nt * 8 + (lane & 3) * 2;
            float bv0 = (c0     < N) ? bias[c0]     : 0.0f;
            float bv1 = (c0 + 1 < N) ? bias[c0 + 1] : 0.0f;
            float v00 = acc[mt][nt][0] + bv0;
            float v01 = acc[mt][nt][1] + bv1;
            float v10 = acc[mt][nt][2] + bv0;
            float v11 = acc[mt][nt][3] + bv1;
            if (RELU) {
                v00 = fmaxf(v00, 0.0f); v01 = fmaxf(v01, 0.0f);
                v10 = fmaxf(v10, 0.0f); v11 = fmaxf(v11, 0.0f);
            }
            if (OUTH) {
                __half* C = (__half*)Cv;
                *reinterpret_cast<__half2*>(C + (size_t)r0 * ldc + c0)
                    = __floats2half2_rn(v00, v01);
                *reinterpret_cast<__half2*>(C + (size_t)(r0 + 8) * ldc + c0)
                    = __floats2half2_rn(v10, v11);
            } else {
                float* C = (float*)Cv;
                if (c0 < N) {
                    C[(size_t)r0 * ldc + c0]       = v00;
                    C[(size_t)(r0 + 8) * ldc + c0] = v10;
                }
                if (c0 + 1 < N) {
                    C[(size_t)r0 * ldc + c0 + 1]       = v01;
                    C[(size_t)(r0 + 8) * ldc + c0 + 1] = v11;
                }
            }
        }
    }
}

// ---------------------------------------------------------------------------
extern "C" void kernel_launch(void* const* d_in, const int* in_sizes, int n_in,
                              void* d_out, int out_size)
{
    (void)in_sizes; (void)n_in; (void)out_size;

    const float* src_graph_vecs = (const float*)d_in[0];
    const float* gvec           = (const float*)d_in[1];
    const float* xnode          = (const float*)d_in[2];
    const float* znode          = (const float*)d_in[3];
    const float* atom_onehot    = (const float*)d_in[4];
    const float* bond_onehot    = (const float*)d_in[5];
    const float* topo_w1        = (const float*)d_in[6];
    const float* topo_b1        = (const float*)d_in[7];
    const float* topo_w2        = (const float*)d_in[8];
    const float* topo_b2        = (const float*)d_in[9];
    const float* atom_w1        = (const float*)d_in[10];
    const float* atom_b1        = (const float*)d_in[11];
    const float* atom_w2        = (const float*)d_in[12];
    const float* atom_b2        = (const float*)d_in[13];
    const float* bond_w1        = (const float*)d_in[14];
    const float* bond_b1        = (const float*)d_in[15];
    const float* bond_w2        = (const float*)d_in[16];
    const float* bond_b2        = (const float*)d_in[17];
    const float* rbond_w        = (const float*)d_in[18];
    const float* rbond_b        = (const float*)d_in[19];
    const float* wbond_w        = (const float*)d_in[20];
    const float* wbond_b        = (const float*)d_in[21];
    const int*   batch_idx      = (const int*)d_in[22];
    float*       out            = (float*)d_out;

    __half *gvh, *xnh, *znh, *ctxh, *aohh, *bohh;
    __half *histh, *curh, *htah, *hbh;
    __half *wtTA, *wtB, *wtR, *wtW, *w2t;
    float  *b2, *bta;
    cudaGetSymbolAddress((void**)&gvh,   g_gvec_h);
    cudaGetSymbolAddress((void**)&xnh,   g_xnode_h);
    cudaGetSymbolAddress((void**)&znh,   g_znode_h);
    cudaGetSymbolAddress((void**)&ctxh,  g_ctx_h);
    cudaGetSymbolAddress((void**)&aohh,  g_aoh_h);
    cudaGetSymbolAddress((void**)&bohh,  g_boh_h);
    cudaGetSymbolAddress((void**)&histh, g_hist_h);
    cudaGetSymbolAddress((void**)&curh,  g_cur_h);
    cudaGetSymbolAddress((void**)&htah,  g_hta_h);
    cudaGetSymbolAddress((void**)&hbh,   g_hb_h);
    cudaGetSymbolAddress((void**)&wtTA,  g_wt_ta);
    cudaGetSymbolAddress((void**)&wtB,   g_wt_bond);
    cudaGetSymbolAddress((void**)&wtR,   g_wt_rbond);
    cudaGetSymbolAddress((void**)&wtW,   g_wt_wbond);
    cudaGetSymbolAddress((void**)&w2t,   g_w2t);
    cudaGetSymbolAddress((void**)&b2,    g_b2);
    cudaGetSymbolAddress((void**)&bta,   g_b_ta);

    cudaFuncSetAttribute(mma_h<2, true, true>,
        cudaFuncAttributeMaxDynamicSharedMemorySize, SMEM_BYTES);
    cudaFuncSetAttribute(mma_h<3, true, true>,
        cudaFuncAttributeMaxDynamicSharedMemorySize, SMEM_BYTES);
    cudaFuncSetAttribute(mma_h<4, true, true>,
        cudaFuncAttributeMaxDynamicSharedMemorySize, SMEM_BYTES);
    cudaFuncSetAttribute(mma_h<2, false, false>,
        cudaFuncAttributeMaxDynamicSharedMemorySize, SMEM_BYTES);

    // ---- pre-pass ----
    const int M = M_ROWS;
    {
        int total = 3 * (M * 128) + M * 16 + M * 32;
        prepass_main<<<(total + 255) / 256, 256>>>(
            gvec, xnode, znode, atom_onehot, src_graph_vecs, batch_idx,
            gvh, xnh, znh, aohh, ctxh);
        pad_boh<<<(M * 8 + 255) / 256, 256>>>(bond_onehot, bohh);
        dim3 tb(32, 8);
        transpose_w<<<dim3(1152 / 32, 512 / 32), tb>>>(topo_w1, wtTA, 1152, 1152, 512);
        transpose_w<<<dim3(1152 / 32, 512 / 32), tb>>>(atom_w1, wtTA + (size_t)512 * 1152,
                                                       1152, 1152, 512);
        transpose_w<<<dim3(1664 / 32, 512 / 32), tb>>>(bond_w1, wtB, 1664, 1664, 512);
        transpose_w<<<dim3(576  / 32, 512 / 32), tb>>>(rbond_w, wtR, 576, 576, 512);
        transpose_w<<<dim3(576  / 32, 512 / 32), tb>>>(wbond_w, wtW, 516, 576, 512);
        build_w2t<<<(128 * 1536 + 255) / 256, 256>>>(topo_w2, topo_b2, atom_w2, atom_b2,
                                                     bond_w2, bond_b2, topo_b1, atom_b1);
    }

    const dim3 blk(256);
    const dim3 grid512(512 / BN, M / BM);    // (4, 256)
    const dim3 grid1024(1024 / BN, M / BM);  // (8, 256)
    const dim3 grid69(1, M / BM);            // (1, 256)

    // K1: hist = relu([znode | boh8] @ wbond), Kpad=576
    {
        SegsH s; s.s[0] = {znh, 512}; s.s[1] = {bohh, 8};
        s.s[2] = {nullptr, 0}; s.s[3] = {nullptr, 0};
        mma_h<2, true, true><<<grid512, blk, SMEM_BYTES>>>(
            512, 576, s, wtW, 576, wbond_b, histh, 512);
    }
    // KF: hta = relu([gvec | xnode | ctx] @ [topo|atom]), K=1152, N=1024
    {
        SegsH s; s.s[0] = {gvh, 512}; s.s[1] = {xnh, 512};
        s.s[2] = {ctxh, 128}; s.s[3] = {nullptr, 0};
        mma_h<3, true, true><<<grid1024, blk, SMEM_BYTES>>>(
            1024, 1152, s, wtTA, 1152, bta, htah, 1024);
    }
    // K2: cur = relu([hist | aoh] @ rbond), K=576
    {
        SegsH s; s.s[0] = {histh, 512}; s.s[1] = {aohh, 64};
        s.s[2] = {nullptr, 0}; s.s[3] = {nullptr, 0};
        mma_h<2, true, true><<<grid512, blk, SMEM_BYTES>>>(
            512, 576, s, wtR, 576, rbond_b, curh, 512);
    }
    // K5: h_b = relu([gvec | cur | znode | ctx] @ bond), K=1664
    {
        SegsH s; s.s[0] = {gvh, 512}; s.s[1] = {curh, 512};
        s.s[2] = {znh, 512}; s.s[3] = {ctxh, 128};
        mma_h<4, true, true><<<grid512, blk, SMEM_BYTES>>>(
            512, 1664, s, wtB, 1664, bond_b1, hbh, 512);
    }
    // K6: out = [hta | h_b] @ W2t + b2, K=1536, N=69 (f32); wn=3 warps idle
    {
        SegsH s; s.s[0] = {htah, 1024}; s.s[1] = {hbh, 512};
        s.s[2] = {nullptr, 0}; s.s[3] = {nullptr, 0};
        mma_h<2, false, false><<<grid69, blk, SMEM_BYTES>>>(
            69, 1536, s, w2t, 1536, b2, out, 69);
    }
}